// round 12
// baseline (speedup 1.0000x reference)
#include <cuda_runtime.h>
#include <cuda_bf16.h>
#include <math.h>
#include <stdint.h>

#define N_TOK   16384
#define E_DIM   512
#define C_DIM   8
#define K_CODES 8192
#define LN_EPS  1e-5f
#define M_SPLIT 8192   // rows [0,M_SPLIT) fp32, [M_SPLIT,N_TOK) bf16-hmma

// ---------------- scratch (device globals: no allocation allowed) ----------------
__device__ float g_h[N_TOK * E_DIM];        // relu(features@W1_in+b1)   32MB
__device__ float g_z[N_TOK * C_DIM];        // layernormed code-space
__device__ unsigned long long g_key[N_TOK]; // packed (dist,idx) argmin keys
__device__ float g_tpre[K_CODES * E_DIM];   // pre-LN table              16MB
__device__ float g_tbl[K_CODES * E_DIM];    // final per-code output     16MB

// bf16 split operands
__device__ __nv_bfloat16 g_hq_hi[K_CODES * E_DIM];
__device__ __nv_bfloat16 g_hq_lo[K_CODES * E_DIM];
__device__ __nv_bfloat16 g_w2_hi[E_DIM * E_DIM];
__device__ __nv_bfloat16 g_w2_lo[E_DIM * E_DIM];
__device__ __nv_bfloat16 g_fhi[N_TOK * E_DIM];   // features 3-way split (2nd half used)
__device__ __nv_bfloat16 g_fmi[N_TOK * E_DIM];
__device__ __nv_bfloat16 g_flo[N_TOK * E_DIM];
__device__ __nv_bfloat16 g_w1hi[E_DIM * E_DIM];  // W1_in split [k][n]
__device__ __nv_bfloat16 g_w1mi[E_DIM * E_DIM];
__device__ __nv_bfloat16 g_w1lo[E_DIM * E_DIM];

// ---------------- common HMMA helpers ----------------
__device__ __forceinline__ uint32_t smem_u32(const void* p) {
    return (uint32_t)__cvta_generic_to_shared(p);
}
#define LDSM_X4(r0,r1,r2,r3,addr) \
    asm volatile("ldmatrix.sync.aligned.m8n8.x4.shared.b16 {%0,%1,%2,%3},[%4];" \
        : "=r"(r0),"=r"(r1),"=r"(r2),"=r"(r3) : "r"(addr))
#define LDSM_X4T(r0,r1,r2,r3,addr) \
    asm volatile("ldmatrix.sync.aligned.m8n8.x4.trans.shared.b16 {%0,%1,%2,%3},[%4];" \
        : "=r"(r0),"=r"(r1),"=r"(r2),"=r"(r3) : "r"(addr))
#define MMA_BF16(d, a, b) \
    asm volatile("mma.sync.aligned.m16n8k16.row.col.f32.bf16.bf16.f32 " \
        "{%0,%1,%2,%3},{%4,%5,%6,%7},{%8,%9},{%0,%1,%2,%3};" \
        : "+f"(d[0]),"+f"(d[1]),"+f"(d[2]),"+f"(d[3]) \
        : "r"(a[0]),"r"(a[1]),"r"(a[2]),"r"(a[3]),"r"(b[0]),"r"(b[1]))

// ---------------- fp32 SGEMM: C = act(A[MxK] @ B[KxN] + bias) ----------------
template <int DO_RELU>
__global__ __launch_bounds__(256) void sgemm_bias(
    int M, int Nn, int Kd,
    const float* __restrict__ A, const float* __restrict__ B,
    const float* __restrict__ bias, float* __restrict__ C)
{
    const int BM = 128, BN = 128, BK = 16, TM = 8, TN = 8;
    __shared__ float As[BK][BM];
    __shared__ float Bs[BK][BN];

    int tid  = threadIdx.x;
    int crow = blockIdx.y * BM;
    int ccol = blockIdx.x * BN;

    int aRow = tid >> 2;
    int aCol = (tid & 3) << 2;
    int bRow = tid >> 5;
    int bCol = (tid & 31) << 2;

    int trow = (tid >> 4) << 3;
    int tcol = (tid & 15) << 3;

    const float* Ap = A + (size_t)crow * Kd;
    const float* Bp = B + ccol;

    float acc[TM][TN];
#pragma unroll
    for (int i = 0; i < TM; i++)
#pragma unroll
        for (int j = 0; j < TN; j++) acc[i][j] = 0.f;

    for (int k0 = 0; k0 < Kd; k0 += BK) {
#pragma unroll
        for (int r = 0; r < 2; r++) {
            float4 v = *(const float4*)(Ap + (size_t)(aRow + 64 * r) * Kd + k0 + aCol);
            As[aCol + 0][aRow + 64 * r] = v.x;
            As[aCol + 1][aRow + 64 * r] = v.y;
            As[aCol + 2][aRow + 64 * r] = v.z;
            As[aCol + 3][aRow + 64 * r] = v.w;
        }
#pragma unroll
        for (int r = 0; r < 2; r++) {
            *(float4*)(&Bs[bRow + 8 * r][bCol]) =
                *(const float4*)(Bp + (size_t)(k0 + bRow + 8 * r) * Nn + bCol);
        }
        __syncthreads();
#pragma unroll
        for (int k = 0; k < BK; k++) {
            float regM[TM], regN[TN];
            *(float4*)&regM[0] = *(const float4*)&As[k][trow];
            *(float4*)&regM[4] = *(const float4*)&As[k][trow + 4];
            *(float4*)&regN[0] = *(const float4*)&Bs[k][tcol];
            *(float4*)&regN[4] = *(const float4*)&Bs[k][tcol + 4];
#pragma unroll
            for (int i = 0; i < TM; i++)
#pragma unroll
                for (int j = 0; j < TN; j++)
                    acc[i][j] = fmaf(regM[i], regN[j], acc[i][j]);
        }
        __syncthreads();
    }

#pragma unroll
    for (int i = 0; i < TM; i++) {
#pragma unroll
        for (int j4 = 0; j4 < TN; j4 += 4) {
            float4 bv = *(const float4*)(bias + ccol + tcol + j4);
            float4 o;
            o.x = acc[i][j4 + 0] + bv.x;
            o.y = acc[i][j4 + 1] + bv.y;
            o.z = acc[i][j4 + 2] + bv.z;
            o.w = acc[i][j4 + 3] + bv.w;
            if (DO_RELU) {
                o.x = fmaxf(o.x, 0.f); o.y = fmaxf(o.y, 0.f);
                o.z = fmaxf(o.z, 0.f); o.w = fmaxf(o.w, 0.f);
            }
            *(float4*)(C + (size_t)(crow + trow + i) * Nn + ccol + tcol + j4) = o;
        }
    }
}

// ---------------- 3-way bf16 split ----------------
__global__ void split3(const float* __restrict__ x,
                       __nv_bfloat16* __restrict__ hi,
                       __nv_bfloat16* __restrict__ mi,
                       __nv_bfloat16* __restrict__ lo)
{
    int i = blockIdx.x * 256 + threadIdx.x;
    float v = x[i];
    __nv_bfloat16 h = __float2bfloat16(v);
    float r = v - __bfloat162float(h);
    __nv_bfloat16 m = __float2bfloat16(r);
    float r2 = r - __bfloat162float(m);
    hi[i] = h; mi[i] = m; lo[i] = __float2bfloat16(r2);
}

// ---------------- GEMM1 (rows >= M_SPLIT): bf16 6-product HMMA ------------------
#define A3ST 24
#define B3ST 136

__global__ __launch_bounds__(256, 1) void hmma3_gemm1(
    int row0, const float* __restrict__ bias, float* __restrict__ C)
{
    __shared__ __align__(16) __nv_bfloat16 sAh[128 * A3ST];
    __shared__ __align__(16) __nv_bfloat16 sAm[128 * A3ST];
    __shared__ __align__(16) __nv_bfloat16 sAl[128 * A3ST];
    __shared__ __align__(16) __nv_bfloat16 sBh[16 * B3ST];
    __shared__ __align__(16) __nv_bfloat16 sBm[16 * B3ST];
    __shared__ __align__(16) __nv_bfloat16 sBl[16 * B3ST];

    int tid = threadIdx.x, lane = tid & 31, warp = tid >> 5;
    int wm = warp >> 2, wn = warp & 3;
    int crow = row0 + blockIdx.y * 128, ccol = blockIdx.x * 128;

    float acc[4][4][4];
#pragma unroll
    for (int mi = 0; mi < 4; mi++)
#pragma unroll
        for (int ni = 0; ni < 4; ni++)
#pragma unroll
            for (int r = 0; r < 4; r++) acc[mi][ni][r] = 0.f;

    for (int kt = 0; kt < 32; kt++) {
        int k0 = kt * 16;
        if (kt) __syncthreads();
        {
            int r = tid >> 1, c8 = (tid & 1) * 8;
            size_t go = (size_t)(crow + r) * 512 + k0 + c8;
            *(uint4*)&sAh[r * A3ST + c8] = *(const uint4*)&g_fhi[go];
            *(uint4*)&sAm[r * A3ST + c8] = *(const uint4*)&g_fmi[go];
            *(uint4*)&sAl[r * A3ST + c8] = *(const uint4*)&g_flo[go];
            int rb = tid >> 4, cb = (tid & 15) * 8;
            size_t gb = (size_t)(k0 + rb) * 512 + ccol + cb;
            *(uint4*)&sBh[rb * B3ST + cb] = *(const uint4*)&g_w1hi[gb];
            *(uint4*)&sBm[rb * B3ST + cb] = *(const uint4*)&g_w1mi[gb];
            *(uint4*)&sBl[rb * B3ST + cb] = *(const uint4*)&g_w1lo[gb];
        }
        __syncthreads();

        uint32_t afh[4][4], afm[4][4], afl[4][4];
#pragma unroll
        for (int mi = 0; mi < 4; mi++) {
            int row = wm * 64 + mi * 16 + (lane & 15);
            int col = (lane >> 4) << 3;
            LDSM_X4(afh[mi][0], afh[mi][1], afh[mi][2], afh[mi][3],
                    smem_u32(&sAh[row * A3ST + col]));
            LDSM_X4(afm[mi][0], afm[mi][1], afm[mi][2], afm[mi][3],
                    smem_u32(&sAm[row * A3ST + col]));
            LDSM_X4(afl[mi][0], afl[mi][1], afl[mi][2], afl[mi][3],
                    smem_u32(&sAl[row * A3ST + col]));
        }
        uint32_t bfr[4][2];
#pragma unroll
        for (int nq = 0; nq < 2; nq++) {
            int krow = lane & 15;
            int col  = wn * 32 + nq * 16 + ((lane >> 4) << 3);
            uint32_t r0, r1, r2, r3;
            LDSM_X4T(r0, r1, r2, r3, smem_u32(&sBh[krow * B3ST + col]));
            bfr[nq * 2][0] = r0; bfr[nq * 2][1] = r1;
            bfr[nq * 2 + 1][0] = r2; bfr[nq * 2 + 1][1] = r3;
        }
#pragma unroll
        for (int mi = 0; mi < 4; mi++)
#pragma unroll
            for (int ni = 0; ni < 4; ni++) {
                MMA_BF16(acc[mi][ni], afh[mi], bfr[ni]);
                MMA_BF16(acc[mi][ni], afm[mi], bfr[ni]);
                MMA_BF16(acc[mi][ni], afl[mi], bfr[ni]);
            }
#pragma unroll
        for (int nq = 0; nq < 2; nq++) {
            int krow = lane & 15;
            int col  = wn * 32 + nq * 16 + ((lane >> 4) << 3);
            uint32_t r0, r1, r2, r3;
            LDSM_X4T(r0, r1, r2, r3, smem_u32(&sBm[krow * B3ST + col]));
            bfr[nq * 2][0] = r0; bfr[nq * 2][1] = r1;
            bfr[nq * 2 + 1][0] = r2; bfr[nq * 2 + 1][1] = r3;
        }
#pragma unroll
        for (int mi = 0; mi < 4; mi++)
#pragma unroll
            for (int ni = 0; ni < 4; ni++) {
                MMA_BF16(acc[mi][ni], afh[mi], bfr[ni]);
                MMA_BF16(acc[mi][ni], afm[mi], bfr[ni]);
            }
#pragma unroll
        for (int nq = 0; nq < 2; nq++) {
            int krow = lane & 15;
            int col  = wn * 32 + nq * 16 + ((lane >> 4) << 3);
            uint32_t r0, r1, r2, r3;
            LDSM_X4T(r0, r1, r2, r3, smem_u32(&sBl[krow * B3ST + col]));
            bfr[nq * 2][0] = r0; bfr[nq * 2][1] = r1;
            bfr[nq * 2 + 1][0] = r2; bfr[nq * 2 + 1][1] = r3;
        }
#pragma unroll
        for (int mi = 0; mi < 4; mi++)
#pragma unroll
            for (int ni = 0; ni < 4; ni++)
                MMA_BF16(acc[mi][ni], afh[mi], bfr[ni]);
    }

    int gr = lane >> 2, gc = (lane & 3) * 2;
#pragma unroll
    for (int mi = 0; mi < 4; mi++)
#pragma unroll
        for (int ni = 0; ni < 4; ni++) {
            int rr = crow + wm * 64 + mi * 16 + gr;
            int cc = ccol + wn * 32 + ni * 8 + gc;
            float b0 = bias[cc], b1 = bias[cc + 1];
            C[(size_t)rr * 512 + cc]           = fmaxf(acc[mi][ni][0] + b0, 0.f);
            C[(size_t)rr * 512 + cc + 1]       = fmaxf(acc[mi][ni][1] + b1, 0.f);
            C[(size_t)(rr + 8) * 512 + cc]     = fmaxf(acc[mi][ni][2] + b0, 0.f);
            C[(size_t)(rr + 8) * 512 + cc + 1] = fmaxf(acc[mi][ni][3] + b1, 0.f);
        }
}

// ---------------- z = LN(h @ W2_in + b2)  — one warp per token ----------------
__global__ __launch_bounds__(256) void gemm2_ln(
    int tok0, const float* __restrict__ h, const float* __restrict__ W2,
    const float* __restrict__ b2, const float* __restrict__ g,
    const float* __restrict__ b, float* __restrict__ z)
{
    __shared__ float w2t[C_DIM * E_DIM];
    int tid = threadIdx.x;
    for (int i = tid; i < C_DIM * E_DIM; i += 256) {
        int c = i >> 9, e = i & 511;
        w2t[i] = W2[e * C_DIM + c];
    }
    __syncthreads();

    int warp = tid >> 5, lane = tid & 31;
    int tok = tok0 + blockIdx.x * 8 + warp;
    const float* hr = h + (size_t)tok * E_DIM;

    float acc[8] = {0.f, 0.f, 0.f, 0.f, 0.f, 0.f, 0.f, 0.f};
#pragma unroll
    for (int i = 0; i < 16; i++) {
        int e = i * 32 + lane;
        float hv = hr[e];
#pragma unroll
        for (int c = 0; c < 8; c++)
            acc[c] = fmaf(hv, w2t[c * 512 + e], acc[c]);
    }
#pragma unroll
    for (int c = 0; c < 8; c++)
#pragma unroll
        for (int off = 16; off > 0; off >>= 1)
            acc[c] += __shfl_xor_sync(0xffffffffu, acc[c], off);

    float zc[8], mu = 0.f;
#pragma unroll
    for (int c = 0; c < 8; c++) { zc[c] = acc[c] + b2[c]; mu += zc[c]; }
    mu *= 0.125f;
    float var = 0.f;
#pragma unroll
    for (int c = 0; c < 8; c++) { float d = zc[c] - mu; var = fmaf(d, d, var); }
    var *= 0.125f;
    float rinv = 1.0f / sqrtf(var + LN_EPS);

    if (lane == 0) {
        float o[8];
#pragma unroll
        for (int c = 0; c < 8; c++) o[c] = (zc[c] - mu) * rinv * g[c] + b[c];
        *(float4*)(z + (size_t)tok * 8)     = make_float4(o[0], o[1], o[2], o[3]);
        *(float4*)(z + (size_t)tok * 8 + 4) = make_float4(o[4], o[5], o[6], o[7]);
    }
}

// ---------------- argmin over codebook (broadcast-LDS, register tokens) ----------
#define CHUNK 512
__global__ __launch_bounds__(256) void argmin_kernel(
    int tok_base, const float* __restrict__ emb, const float* __restrict__ z)
{
    __shared__ float se[CHUNK * 8];
    __shared__ float ss[CHUNK];

    int tid  = threadIdx.x;
    int warp = tid >> 5, lane = tid & 31;
    int c0   = blockIdx.x * CHUNK;
    int tok0 = tok_base + blockIdx.y * 1024 + warp * 128 + lane * 4;

    const float4* src = (const float4*)(emb + (size_t)c0 * 8);
#pragma unroll
    for (int u = 0; u < 4; u++) ((float4*)se)[tid + 256 * u] = src[tid + 256 * u];
    __syncthreads();
#pragma unroll
    for (int u = 0; u < 2; u++) {
        int c = tid + 256 * u;
        const float* e = se + c * 8;
        float s = e[0] * e[0];
#pragma unroll
        for (int j = 1; j < 8; j++) s = fmaf(e[j], e[j], s);
        ss[c] = s;
    }
    __syncthreads();

    float zr[4][8], sz2[4];
#pragma unroll
    for (int t = 0; t < 4; t++) {
        float4 a = *(const float4*)(z + (size_t)(tok0 + t) * 8);
        float4 b = *(const float4*)(z + (size_t)(tok0 + t) * 8 + 4);
        zr[t][0] = a.x; zr[t][1] = a.y; zr[t][2] = a.z; zr[t][3] = a.w;
        zr[t][4] = b.x; zr[t][5] = b.y; zr[t][6] = b.z; zr[t][7] = b.w;
        float s = a.x * a.x;
        s = fmaf(a.y, a.y, s); s = fmaf(a.z, a.z, s); s = fmaf(a.w, a.w, s);
        s = fmaf(b.x, b.x, s); s = fmaf(b.y, b.y, s);
        s = fmaf(b.z, b.z, s); s = fmaf(b.w, b.w, s);
        sz2[t] = s;
    }

    float bestd[4];
    int   besti[4];
#pragma unroll
    for (int t = 0; t < 4; t++) { bestd[t] = __int_as_float(0x7f800000); besti[t] = 0; }

#pragma unroll 2
    for (int c = 0; c < CHUNK; c++) {
        float4 ea = *(const float4*)(se + c * 8);
        float4 eb = *(const float4*)(se + c * 8 + 4);
        float ssc = ss[c];
#pragma unroll
        for (int t = 0; t < 4; t++) {
            float dot = zr[t][0] * ea.x;
            dot = fmaf(zr[t][1], ea.y, dot);
            dot = fmaf(zr[t][2], ea.z, dot);
            dot = fmaf(zr[t][3], ea.w, dot);
            dot = fmaf(zr[t][4], eb.x, dot);
            dot = fmaf(zr[t][5], eb.y, dot);
            dot = fmaf(zr[t][6], eb.z, dot);
            dot = fmaf(zr[t][7], eb.w, dot);
            float d = (sz2[t] - 2.0f * dot) + ssc;
            if (d < bestd[t]) { bestd[t] = d; besti[t] = c0 + c; }
        }
    }

#pragma unroll
    for (int t = 0; t < 4; t++) {
        unsigned int m = __float_as_uint(bestd[t]);
        m = ((int)m < 0) ? ~m : (m | 0x80000000u);
        unsigned long long key = ((unsigned long long)m << 32) | (unsigned)besti[t];
        atomicMin(&g_key[tok0 + t], key);
    }
}

// ---------------- hq = relu(emb @ W1_out + b1) -> bf16 hi/lo split ----------------
__global__ void proj_out1(const float* __restrict__ emb,
                          const float* __restrict__ W1o,
                          const float* __restrict__ b1o)
{
    int i = blockIdx.x * 256 + threadIdx.x;
    int k = i >> 9, e = i & 511;
    const float* er = emb + (size_t)k * 8;
    float acc = er[0] * W1o[e];
#pragma unroll
    for (int c = 1; c < 8; c++) acc = fmaf(er[c], W1o[c * 512 + e], acc);
    float x = fmaxf(acc + b1o[e], 0.f);
    __nv_bfloat16 hi = __float2bfloat16(x);
    g_hq_hi[i] = hi;
    g_hq_lo[i] = __float2bfloat16(x - __bfloat162float(hi));
}

// ---------------- W2_out fp32 -> bf16 hi/lo split ----------------
__global__ void split_w2(const float* __restrict__ W)
{
    int i = blockIdx.x * 256 + threadIdx.x;
    float x = W[i];
    __nv_bfloat16 hi = __float2bfloat16(x);
    g_w2_hi[i] = hi;
    g_w2_lo[i] = __float2bfloat16(x - __bfloat162float(hi));
}

// ---------------- tensor-core table GEMM (bf16 3-term split, validated) ---------
#define AST 40
#define BST 136

__global__ __launch_bounds__(256, 1) void hmma_tbl(
    const float* __restrict__ bias, float* __restrict__ C)
{
    __shared__ __align__(16) __nv_bfloat16 sAhi[128 * AST];
    __shared__ __align__(16) __nv_bfloat16 sAlo[128 * AST];
    __shared__ __align__(16) __nv_bfloat16 sBhi[32 * BST];
    __shared__ __align__(16) __nv_bfloat16 sBlo[32 * BST];

    int tid = threadIdx.x, lane = tid & 31, warp = tid >> 5;
    int wm = warp >> 2, wn = warp & 3;
    int crow = blockIdx.y * 128, ccol = blockIdx.x * 128;

    const __nv_bfloat16* Ahi = g_hq_hi + (size_t)crow * 512;
    const __nv_bfloat16* Alo = g_hq_lo + (size_t)crow * 512;

    float acc[4][4][4];
#pragma unroll
    for (int mi = 0; mi < 4; mi++)
#pragma unroll
        for (int ni = 0; ni < 4; ni++)
#pragma unroll
            for (int r = 0; r < 4; r++) acc[mi][ni][r] = 0.f;

    for (int kt = 0; kt < 16; kt++) {
        int k0 = kt * 32;
        if (kt) __syncthreads();
#pragma unroll
        for (int u = 0; u < 2; u++) {
            int e  = tid + u * 256;
            int r  = e >> 2, c8 = (e & 3) * 8;
            *(uint4*)&sAhi[r * AST + c8] = *(const uint4*)&Ahi[(size_t)r * 512 + k0 + c8];
            *(uint4*)&sAlo[r * AST + c8] = *(const uint4*)&Alo[(size_t)r * 512 + k0 + c8];
            int rb = e >> 4, cb = (e & 15) * 8;
            *(uint4*)&sBhi[rb * BST + cb] = *(const uint4*)&g_w2_hi[(size_t)(k0 + rb) * 512 + ccol + cb];
            *(uint4*)&sBlo[rb * BST + cb] = *(const uint4*)&g_w2_lo[(size_t)(k0 + rb) * 512 + ccol + cb];
        }
        __syncthreads();

#pragma unroll
        for (int ks = 0; ks < 2; ks++) {
            int kk = ks * 16;
            uint32_t afh[4][4], afl[4][4], bfh[4][2], bfl[4][2];
#pragma unroll
            for (int mi = 0; mi < 4; mi++) {
                int row = wm * 64 + mi * 16 + (lane & 15);
                int col = kk + ((lane >> 4) << 3);
                LDSM_X4(afh[mi][0], afh[mi][1], afh[mi][2], afh[mi][3],
                        smem_u32(&sAhi[row * AST + col]));
                LDSM_X4(afl[mi][0], afl[mi][1], afl[mi][2], afl[mi][3],
                        smem_u32(&sAlo[row * AST + col]));
            }
#pragma unroll
            for (int nq = 0; nq < 2; nq++) {
                int krow = kk + (lane & 15);
                int col  = wn * 32 + nq * 16 + ((lane >> 4) << 3);
                uint32_t r0, r1, r2, r3;
                LDSM_X4T(r0, r1, r2, r3, smem_u32(&sBhi[krow * BST + col]));
                bfh[nq * 2][0] = r0; bfh[nq * 2][1] = r1;
                bfh[nq * 2 + 1][0] = r2; bfh[nq * 2 + 1][1] = r3;
                LDSM_X4T(r0, r1, r2, r3, smem_u32(&sBlo[krow * BST + col]));
                bfl[nq * 2][0] = r0; bfl[nq * 2][1] = r1;
                bfl[nq * 2 + 1][0] = r2; bfl[nq * 2 + 1][1] = r3;
            }
#pragma unroll
            for (int mi = 0; mi < 4; mi++)
#pragma unroll
                for (int ni = 0; ni < 4; ni++) {
                    MMA_BF16(acc[mi][ni], afh[mi], bfh[ni]);
                    MMA_BF16(acc[mi][ni], afh[mi], bfl[ni]);
                    MMA_BF16(acc[mi][ni], afl[mi], bfh[ni]);
                }
        }
    }

    int gr = lane >> 2, gc = (lane & 3) * 2;
#pragma unroll
    for (int mi = 0; mi < 4; mi++)
#pragma unroll
        for (int ni = 0; ni < 4; ni++) {
            int rr = crow + wm * 64 + mi * 16 + gr;
            int cc = ccol + wn * 32 + ni * 8 + gc;
            float b0 = bias[cc], b1 = bias[cc + 1];
            C[(size_t)rr * 512 + cc]           = acc[mi][ni][0] + b0;
            C[(size_t)rr * 512 + cc + 1]       = acc[mi][ni][1] + b1;
            C[(size_t)(rr + 8) * 512 + cc]     = acc[mi][ni][2] + b0;
            C[(size_t)(rr + 8) * 512 + cc + 1] = acc[mi][ni][3] + b1;
        }
}

// ---------------- row LayerNorm over E=512 — one warp per row ----------------
__global__ __launch_bounds__(256) void ln_rows(
    const float* __restrict__ x, const float* __restrict__ g,
    const float* __restrict__ b, float* __restrict__ y)
{
    int warp = (blockIdx.x * 256 + threadIdx.x) >> 5;
    int lane = threadIdx.x & 31;
    const float* r = x + (size_t)warp * 512;

    float4 v[4];
    float s = 0.f;
#pragma unroll
    for (int i = 0; i < 4; i++) {
        v[i] = ((const float4*)r)[lane + 32 * i];
        s += v[i].x + v[i].y + v[i].z + v[i].w;
    }
#pragma unroll
    for (int off = 16; off > 0; off >>= 1) s += __shfl_xor_sync(0xffffffffu, s, off);
    float mu = s * (1.0f / 512.0f);

    float s2 = 0.f;
#pragma unroll
    for (int i = 0; i < 4; i++) {
        float dx;
        dx = v[i].x - mu; s2 = fmaf(dx, dx, s2);
        dx = v[i].y - mu; s2 = fmaf(dx, dx, s2);
        dx = v[i].z - mu; s2 = fmaf(dx, dx, s2);
        dx = v[i].w - mu; s2 = fmaf(dx, dx, s2);
    }
#pragma unroll
    for (int off = 16; off > 0; off >>= 1) s2 += __shfl_xor_sync(0xffffffffu, s2, off);
    float var = s2 * (1.0f / 512.0f);
    float inv = 1.0f / sqrtf(var + LN_EPS);

#pragma unroll
    for (int i = 0; i < 4; i++) {
        int e = 4 * (lane + 32 * i);
        float4 gg = *(const float4*)(g + e);
        float4 bb = *(const float4*)(b + e);
        float4 o;
        o.x = (v[i].x - mu) * inv * gg.x + bb.x;
        o.y = (v[i].y - mu) * inv * gg.y + bb.y;
        o.z = (v[i].z - mu) * inv * gg.z + bb.z;
        o.w = (v[i].w - mu) * inv * gg.w + bb.w;
        ((float4*)(y + (size_t)warp * 512))[lane + 32 * i] = o;
    }
}

// ---------------- gather: q rows, idx (as float), one-hot scatter ----------------
__global__ void gather_out(float* __restrict__ outq, float* __restrict__ outidx,
                           float* __restrict__ outenc)
{
    int tok = blockIdx.x;
    int k = (int)(g_key[tok] & 0xFFFFFFFFull);
    int t = threadIdx.x;
    float4 v = ((const float4*)(g_tbl + (size_t)k * 512))[t];
    ((float4*)(outq + (size_t)tok * 512))[t] = v;
    if (t == 0) {
        if (outidx) outidx[tok] = (float)k;
        if (outenc) outenc[(size_t)tok * K_CODES + k] = 1.0f;
    }
}

// ---------------- launch ----------------
extern "C" void kernel_launch(void* const* d_in, const int* in_sizes, int n_in,
                              void* d_out, int out_size)
{
    const float* features = (const float*)d_in[0];
    const float* W1_in    = (const float*)d_in[1];
    const float* b1_in    = (const float*)d_in[2];
    const float* W2_in    = (const float*)d_in[3];
    const float* b2_in    = (const float*)d_in[4];
    const float* ln_in_g  = (const float*)d_in[5];
    const float* ln_in_b  = (const float*)d_in[6];
    const float* emb      = (const float*)d_in[7];
    const float* W1_out   = (const float*)d_in[8];
    const float* b1_out   = (const float*)d_in[9];
    const float* W2_out   = (const float*)d_in[10];
    const float* b2_out   = (const float*)d_in[11];
    const float* ln_out_g = (const float*)d_in[12];
    const float* ln_out_b = (const float*)d_in[13];

    float* out = (float*)d_out;
    const long long q_elems   = (long long)N_TOK * E_DIM;
    const long long idx_elems = N_TOK;
    const long long enc_elems = (long long)N_TOK * K_CODES;
    float* outq   = out;
    float* outidx = nullptr;
    float* outenc = nullptr;
    if ((long long)out_size >= q_elems + idx_elems + enc_elems) {
        outidx = out + q_elems;
        outenc = out + q_elems + idx_elems;
    } else if ((long long)out_size >= q_elems + idx_elems) {
        outidx = out + q_elems;
    }

    float *p_h, *p_z, *p_tpre, *p_tbl;
    __nv_bfloat16 *p_fhi, *p_fmi, *p_flo, *p_w1hi, *p_w1mi, *p_w1lo;
    void* p_key;
    cudaGetSymbolAddress((void**)&p_h,    g_h);
    cudaGetSymbolAddress((void**)&p_z,    g_z);
    cudaGetSymbolAddress((void**)&p_tpre, g_tpre);
    cudaGetSymbolAddress((void**)&p_tbl,  g_tbl);
    cudaGetSymbolAddress((void**)&p_fhi,  g_fhi);
    cudaGetSymbolAddress((void**)&p_fmi,  g_fmi);
    cudaGetSymbolAddress((void**)&p_flo,  g_flo);
    cudaGetSymbolAddress((void**)&p_w1hi, g_w1hi);
    cudaGetSymbolAddress((void**)&p_w1mi, g_w1mi);
    cudaGetSymbolAddress((void**)&p_w1lo, g_w1lo);
    cudaGetSymbolAddress(&p_key, g_key);

    // streams: B = codebook table, C = encodings memset, D = hmma token pipeline
    static cudaStream_t sB = nullptr, sC = nullptr, sD = nullptr;
    static cudaEvent_t evF = nullptr, evB = nullptr, evC = nullptr, evD = nullptr,
                       evK = nullptr;
    if (!sB) {
        cudaStreamCreateWithFlags(&sB, cudaStreamNonBlocking);
        cudaStreamCreateWithFlags(&sC, cudaStreamNonBlocking);
        cudaStreamCreateWithFlags(&sD, cudaStreamNonBlocking);
        cudaEventCreateWithFlags(&evF, cudaEventDisableTiming);
        cudaEventCreateWithFlags(&evB, cudaEventDisableTiming);
        cudaEventCreateWithFlags(&evC, cudaEventDisableTiming);
        cudaEventCreateWithFlags(&evD, cudaEventDisableTiming);
        cudaEventCreateWithFlags(&evK, cudaEventDisableTiming);
    }

    cudaEventRecord(evF, 0);
    cudaStreamWaitEvent(sB, evF, 0);
    cudaStreamWaitEvent(sC, evF, 0);
    cudaStreamWaitEvent(sD, evF, 0);

    // ---- stream C: encodings memset (pure DRAM, hides under compute) ----
    if (outenc)
        cudaMemsetAsync(outenc, 0, (size_t)enc_elems * sizeof(float), sC);
    cudaEventRecord(evC, sC);

    // ---- stream B: codebook output table (validated bf16 tensor path) ----
    split_w2<<<(E_DIM * E_DIM) / 256, 256, 0, sB>>>(W2_out);
    proj_out1<<<(K_CODES * E_DIM) / 256, 256, 0, sB>>>(emb, W1_out, b1_out);
    dim3 g2(E_DIM / 128, K_CODES / 128);
    hmma_tbl<<<g2, 256, 0, sB>>>(b2_out, p_tpre);
    ln_rows<<<K_CODES / 8, 256, 0, sB>>>(p_tpre, ln_out_g, ln_out_b, p_tbl);
    cudaEventRecord(evB, sB);

    // ---- stream 0: g_key init (gates both argmin halves) ----
    cudaMemsetAsync(p_key, 0xFF, N_TOK * sizeof(unsigned long long), 0);
    cudaEventRecord(evK, 0);

    // ---- stream D: bf16 token pipeline (rows M_SPLIT..N_TOK) ----
    {
        const size_t off = (size_t)M_SPLIT * E_DIM;
        split3<<<((N_TOK - M_SPLIT) * E_DIM) / 256, 256, 0, sD>>>(
            features + off, p_fhi + off, p_fmi + off, p_flo + off);
        split3<<<(E_DIM * E_DIM) / 256, 256, 0, sD>>>(
            W1_in, p_w1hi, p_w1mi, p_w1lo);
        dim3 gd(E_DIM / 128, (N_TOK - M_SPLIT) / 128);
        hmma3_gemm1<<<gd, 256, 0, sD>>>(M_SPLIT, b1_in, p_h);
        gemm2_ln<<<(N_TOK - M_SPLIT) / 8, 256, 0, sD>>>(
            M_SPLIT, p_h, W2_in, b2_in, ln_in_g, ln_in_b, p_z);
        cudaStreamWaitEvent(sD, evK, 0);
        argmin_kernel<<<dim3(K_CODES / CHUNK, (N_TOK - M_SPLIT) / 1024), 256, 0, sD>>>(
            M_SPLIT, emb, p_z);
    }
    cudaEventRecord(evD, sD);

    // ---- stream 0: fp32 token pipeline (rows 0..M_SPLIT) ----
    dim3 g1(E_DIM / 128, M_SPLIT / 128);
    sgemm_bias<1><<<g1, 256>>>(M_SPLIT, E_DIM, E_DIM, features, W1_in, b1_in, p_h);
    gemm2_ln<<<M_SPLIT / 8, 256>>>(0, p_h, W2_in, b2_in, ln_in_g, ln_in_b, p_z);
    argmin_kernel<<<dim3(K_CODES / CHUNK, M_SPLIT / 1024), 256>>>(0, emb, p_z);

    // join + final gather
    cudaStreamWaitEvent(0, evD, 0);
    cudaStreamWaitEvent(0, evB, 0);
    cudaStreamWaitEvent(0, evC, 0);
    gather_out<<<N_TOK, 128>>>(outq, outidx, outenc);
}

// round 13
// speedup vs baseline: 1.0747x; 1.0747x over previous
#include <cuda_runtime.h>
#include <cuda_bf16.h>
#include <math.h>
#include <stdint.h>

#define N_TOK   16384
#define E_DIM   512
#define C_DIM   8
#define K_CODES 8192
#define LN_EPS  1e-5f
#define M_SPLIT 8192   // rows [0,M_SPLIT) fp32, [M_SPLIT,N_TOK) bf16-hmma

// ---------------- scratch (device globals: no allocation allowed) ----------------
__device__ float g_h[N_TOK * E_DIM];        // relu(features@W1_in+b1)   32MB
__device__ float g_z[N_TOK * C_DIM];        // layernormed code-space
__device__ unsigned long long g_key[N_TOK]; // packed (dist,idx) argmin keys
__device__ float g_tpre[K_CODES * E_DIM];   // pre-LN table              16MB
__device__ float g_tbl[K_CODES * E_DIM];    // final per-code output     16MB

// bf16 split operands
__device__ __nv_bfloat16 g_hq_hi[K_CODES * E_DIM];
__device__ __nv_bfloat16 g_hq_lo[K_CODES * E_DIM];
__device__ __nv_bfloat16 g_w2_hi[E_DIM * E_DIM];
__device__ __nv_bfloat16 g_w2_lo[E_DIM * E_DIM];
__device__ __nv_bfloat16 g_fhi[N_TOK * E_DIM];   // features 3-way split (2nd half used)
__device__ __nv_bfloat16 g_fmi[N_TOK * E_DIM];
__device__ __nv_bfloat16 g_flo[N_TOK * E_DIM];
__device__ __nv_bfloat16 g_w1hi[E_DIM * E_DIM];  // W1_in split [k][n]
__device__ __nv_bfloat16 g_w1mi[E_DIM * E_DIM];
__device__ __nv_bfloat16 g_w1lo[E_DIM * E_DIM];

// ---------------- common HMMA helpers ----------------
__device__ __forceinline__ uint32_t smem_u32(const void* p) {
    return (uint32_t)__cvta_generic_to_shared(p);
}
#define LDSM_X4(r0,r1,r2,r3,addr) \
    asm volatile("ldmatrix.sync.aligned.m8n8.x4.shared.b16 {%0,%1,%2,%3},[%4];" \
        : "=r"(r0),"=r"(r1),"=r"(r2),"=r"(r3) : "r"(addr))
#define LDSM_X4T(r0,r1,r2,r3,addr) \
    asm volatile("ldmatrix.sync.aligned.m8n8.x4.trans.shared.b16 {%0,%1,%2,%3},[%4];" \
        : "=r"(r0),"=r"(r1),"=r"(r2),"=r"(r3) : "r"(addr))
#define MMA_BF16(d, a, b) \
    asm volatile("mma.sync.aligned.m16n8k16.row.col.f32.bf16.bf16.f32 " \
        "{%0,%1,%2,%3},{%4,%5,%6,%7},{%8,%9},{%0,%1,%2,%3};" \
        : "+f"(d[0]),"+f"(d[1]),"+f"(d[2]),"+f"(d[3]) \
        : "r"(a[0]),"r"(a[1]),"r"(a[2]),"r"(a[3]),"r"(b[0]),"r"(b[1]))

// ---------------- fp32 SGEMM: C = act(A[MxK] @ B[KxN] + bias) ----------------
template <int DO_RELU>
__global__ __launch_bounds__(256) void sgemm_bias(
    int M, int Nn, int Kd,
    const float* __restrict__ A, const float* __restrict__ B,
    const float* __restrict__ bias, float* __restrict__ C)
{
    const int BM = 128, BN = 128, BK = 16, TM = 8, TN = 8;
    __shared__ float As[BK][BM];
    __shared__ float Bs[BK][BN];

    int tid  = threadIdx.x;
    int crow = blockIdx.y * BM;
    int ccol = blockIdx.x * BN;

    int aRow = tid >> 2;
    int aCol = (tid & 3) << 2;
    int bRow = tid >> 5;
    int bCol = (tid & 31) << 2;

    int trow = (tid >> 4) << 3;
    int tcol = (tid & 15) << 3;

    const float* Ap = A + (size_t)crow * Kd;
    const float* Bp = B + ccol;

    float acc[TM][TN];
#pragma unroll
    for (int i = 0; i < TM; i++)
#pragma unroll
        for (int j = 0; j < TN; j++) acc[i][j] = 0.f;

    for (int k0 = 0; k0 < Kd; k0 += BK) {
#pragma unroll
        for (int r = 0; r < 2; r++) {
            float4 v = *(const float4*)(Ap + (size_t)(aRow + 64 * r) * Kd + k0 + aCol);
            As[aCol + 0][aRow + 64 * r] = v.x;
            As[aCol + 1][aRow + 64 * r] = v.y;
            As[aCol + 2][aRow + 64 * r] = v.z;
            As[aCol + 3][aRow + 64 * r] = v.w;
        }
#pragma unroll
        for (int r = 0; r < 2; r++) {
            *(float4*)(&Bs[bRow + 8 * r][bCol]) =
                *(const float4*)(Bp + (size_t)(k0 + bRow + 8 * r) * Nn + bCol);
        }
        __syncthreads();
#pragma unroll
        for (int k = 0; k < BK; k++) {
            float regM[TM], regN[TN];
            *(float4*)&regM[0] = *(const float4*)&As[k][trow];
            *(float4*)&regM[4] = *(const float4*)&As[k][trow + 4];
            *(float4*)&regN[0] = *(const float4*)&Bs[k][tcol];
            *(float4*)&regN[4] = *(const float4*)&Bs[k][tcol + 4];
#pragma unroll
            for (int i = 0; i < TM; i++)
#pragma unroll
                for (int j = 0; j < TN; j++)
                    acc[i][j] = fmaf(regM[i], regN[j], acc[i][j]);
        }
        __syncthreads();
    }

#pragma unroll
    for (int i = 0; i < TM; i++) {
#pragma unroll
        for (int j4 = 0; j4 < TN; j4 += 4) {
            float4 bv = *(const float4*)(bias + ccol + tcol + j4);
            float4 o;
            o.x = acc[i][j4 + 0] + bv.x;
            o.y = acc[i][j4 + 1] + bv.y;
            o.z = acc[i][j4 + 2] + bv.z;
            o.w = acc[i][j4 + 3] + bv.w;
            if (DO_RELU) {
                o.x = fmaxf(o.x, 0.f); o.y = fmaxf(o.y, 0.f);
                o.z = fmaxf(o.z, 0.f); o.w = fmaxf(o.w, 0.f);
            }
            *(float4*)(C + (size_t)(crow + trow + i) * Nn + ccol + tcol + j4) = o;
        }
    }
}

// ---------------- 3-way bf16 split ----------------
__global__ void split3(const float* __restrict__ x,
                       __nv_bfloat16* __restrict__ hi,
                       __nv_bfloat16* __restrict__ mi,
                       __nv_bfloat16* __restrict__ lo)
{
    int i = blockIdx.x * 256 + threadIdx.x;
    float v = x[i];
    __nv_bfloat16 h = __float2bfloat16(v);
    float r = v - __bfloat162float(h);
    __nv_bfloat16 m = __float2bfloat16(r);
    float r2 = r - __bfloat162float(m);
    hi[i] = h; mi[i] = m; lo[i] = __float2bfloat16(r2);
}

// ---------------- GEMM1 (rows >= M_SPLIT): bf16 6-product HMMA ------------------
// Register-prefetch version: next tile's LDGs issue before the MMA block so the
// global-load latency hides under tensor work. Arithmetic identical to the
// validated round-9/11 kernel (same MMAs, same order).
#define A3ST 24
#define B3ST 136

__global__ __launch_bounds__(256, 1) void hmma3_gemm1(
    int row0, const float* __restrict__ bias, float* __restrict__ C)
{
    __shared__ __align__(16) __nv_bfloat16 sAh[128 * A3ST];
    __shared__ __align__(16) __nv_bfloat16 sAm[128 * A3ST];
    __shared__ __align__(16) __nv_bfloat16 sAl[128 * A3ST];
    __shared__ __align__(16) __nv_bfloat16 sBh[16 * B3ST];
    __shared__ __align__(16) __nv_bfloat16 sBm[16 * B3ST];
    __shared__ __align__(16) __nv_bfloat16 sBl[16 * B3ST];

    int tid = threadIdx.x, lane = tid & 31, warp = tid >> 5;
    int wm = warp >> 2, wn = warp & 3;
    int crow = row0 + blockIdx.y * 128, ccol = blockIdx.x * 128;

    int ra = tid >> 1, c8 = (tid & 1) * 8;      // A staging coords
    int rb = tid >> 4, cb = (tid & 15) * 8;     // B staging coords

    float acc[4][4][4];
#pragma unroll
    for (int mi = 0; mi < 4; mi++)
#pragma unroll
        for (int ni = 0; ni < 4; ni++)
#pragma unroll
            for (int r = 0; r < 4; r++) acc[mi][ni][r] = 0.f;

    uint4 pA0, pA1, pA2, pB0, pB1, pB2;
    {   // prefetch kt = 0
        size_t go = (size_t)(crow + ra) * 512 + c8;
        pA0 = *(const uint4*)&g_fhi[go];
        pA1 = *(const uint4*)&g_fmi[go];
        pA2 = *(const uint4*)&g_flo[go];
        size_t gb = (size_t)rb * 512 + ccol + cb;
        pB0 = *(const uint4*)&g_w1hi[gb];
        pB1 = *(const uint4*)&g_w1mi[gb];
        pB2 = *(const uint4*)&g_w1lo[gb];
    }

    for (int kt = 0; kt < 32; kt++) {
        if (kt) __syncthreads();                 // prior compute done reading smem
        *(uint4*)&sAh[ra * A3ST + c8] = pA0;
        *(uint4*)&sAm[ra * A3ST + c8] = pA1;
        *(uint4*)&sAl[ra * A3ST + c8] = pA2;
        *(uint4*)&sBh[rb * B3ST + cb] = pB0;
        *(uint4*)&sBm[rb * B3ST + cb] = pB1;
        *(uint4*)&sBl[rb * B3ST + cb] = pB2;
        __syncthreads();

        if (kt + 1 < 32) {                       // prefetch next tile (hides LDG)
            int k0 = (kt + 1) * 16;
            size_t go = (size_t)(crow + ra) * 512 + k0 + c8;
            pA0 = *(const uint4*)&g_fhi[go];
            pA1 = *(const uint4*)&g_fmi[go];
            pA2 = *(const uint4*)&g_flo[go];
            size_t gb = (size_t)(k0 + rb) * 512 + ccol + cb;
            pB0 = *(const uint4*)&g_w1hi[gb];
            pB1 = *(const uint4*)&g_w1mi[gb];
            pB2 = *(const uint4*)&g_w1lo[gb];
        }

        uint32_t afh[4][4], afm[4][4], afl[4][4];
#pragma unroll
        for (int mi = 0; mi < 4; mi++) {
            int row = wm * 64 + mi * 16 + (lane & 15);
            int col = (lane >> 4) << 3;
            LDSM_X4(afh[mi][0], afh[mi][1], afh[mi][2], afh[mi][3],
                    smem_u32(&sAh[row * A3ST + col]));
            LDSM_X4(afm[mi][0], afm[mi][1], afm[mi][2], afm[mi][3],
                    smem_u32(&sAm[row * A3ST + col]));
            LDSM_X4(afl[mi][0], afl[mi][1], afl[mi][2], afl[mi][3],
                    smem_u32(&sAl[row * A3ST + col]));
        }
        uint32_t bfr[4][2];
#pragma unroll
        for (int nq = 0; nq < 2; nq++) {
            int krow = lane & 15;
            int col  = wn * 32 + nq * 16 + ((lane >> 4) << 3);
            uint32_t r0, r1, r2, r3;
            LDSM_X4T(r0, r1, r2, r3, smem_u32(&sBh[krow * B3ST + col]));
            bfr[nq * 2][0] = r0; bfr[nq * 2][1] = r1;
            bfr[nq * 2 + 1][0] = r2; bfr[nq * 2 + 1][1] = r3;
        }
#pragma unroll
        for (int mi = 0; mi < 4; mi++)
#pragma unroll
            for (int ni = 0; ni < 4; ni++) {
                MMA_BF16(acc[mi][ni], afh[mi], bfr[ni]);
                MMA_BF16(acc[mi][ni], afm[mi], bfr[ni]);
                MMA_BF16(acc[mi][ni], afl[mi], bfr[ni]);
            }
#pragma unroll
        for (int nq = 0; nq < 2; nq++) {
            int krow = lane & 15;
            int col  = wn * 32 + nq * 16 + ((lane >> 4) << 3);
            uint32_t r0, r1, r2, r3;
            LDSM_X4T(r0, r1, r2, r3, smem_u32(&sBm[krow * B3ST + col]));
            bfr[nq * 2][0] = r0; bfr[nq * 2][1] = r1;
            bfr[nq * 2 + 1][0] = r2; bfr[nq * 2 + 1][1] = r3;
        }
#pragma unroll
        for (int mi = 0; mi < 4; mi++)
#pragma unroll
            for (int ni = 0; ni < 4; ni++) {
                MMA_BF16(acc[mi][ni], afh[mi], bfr[ni]);
                MMA_BF16(acc[mi][ni], afm[mi], bfr[ni]);
            }
#pragma unroll
        for (int nq = 0; nq < 2; nq++) {
            int krow = lane & 15;
            int col  = wn * 32 + nq * 16 + ((lane >> 4) << 3);
            uint32_t r0, r1, r2, r3;
            LDSM_X4T(r0, r1, r2, r3, smem_u32(&sBl[krow * B3ST + col]));
            bfr[nq * 2][0] = r0; bfr[nq * 2][1] = r1;
            bfr[nq * 2 + 1][0] = r2; bfr[nq * 2 + 1][1] = r3;
        }
#pragma unroll
        for (int mi = 0; mi < 4; mi++)
#pragma unroll
            for (int ni = 0; ni < 4; ni++)
                MMA_BF16(acc[mi][ni], afh[mi], bfr[ni]);
    }

    int gr = lane >> 2, gc = (lane & 3) * 2;
#pragma unroll
    for (int mi = 0; mi < 4; mi++)
#pragma unroll
        for (int ni = 0; ni < 4; ni++) {
            int rr = crow + wm * 64 + mi * 16 + gr;
            int cc = ccol + wn * 32 + ni * 8 + gc;
            float b0 = bias[cc], b1 = bias[cc + 1];
            C[(size_t)rr * 512 + cc]           = fmaxf(acc[mi][ni][0] + b0, 0.f);
            C[(size_t)rr * 512 + cc + 1]       = fmaxf(acc[mi][ni][1] + b1, 0.f);
            C[(size_t)(rr + 8) * 512 + cc]     = fmaxf(acc[mi][ni][2] + b0, 0.f);
            C[(size_t)(rr + 8) * 512 + cc + 1] = fmaxf(acc[mi][ni][3] + b1, 0.f);
        }
}

// ---------------- z = LN(h @ W2_in + b2)  — one warp per token ----------------
__global__ __launch_bounds__(256) void gemm2_ln(
    int tok0, const float* __restrict__ h, const float* __restrict__ W2,
    const float* __restrict__ b2, const float* __restrict__ g,
    const float* __restrict__ b, float* __restrict__ z)
{
    __shared__ float w2t[C_DIM * E_DIM];
    int tid = threadIdx.x;
    for (int i = tid; i < C_DIM * E_DIM; i += 256) {
        int c = i >> 9, e = i & 511;
        w2t[i] = W2[e * C_DIM + c];
    }
    __syncthreads();

    int warp = tid >> 5, lane = tid & 31;
    int tok = tok0 + blockIdx.x * 8 + warp;
    const float* hr = h + (size_t)tok * E_DIM;

    float acc[8] = {0.f, 0.f, 0.f, 0.f, 0.f, 0.f, 0.f, 0.f};
#pragma unroll
    for (int i = 0; i < 16; i++) {
        int e = i * 32 + lane;
        float hv = hr[e];
#pragma unroll
        for (int c = 0; c < 8; c++)
            acc[c] = fmaf(hv, w2t[c * 512 + e], acc[c]);
    }
#pragma unroll
    for (int c = 0; c < 8; c++)
#pragma unroll
        for (int off = 16; off > 0; off >>= 1)
            acc[c] += __shfl_xor_sync(0xffffffffu, acc[c], off);

    float zc[8], mu = 0.f;
#pragma unroll
    for (int c = 0; c < 8; c++) { zc[c] = acc[c] + b2[c]; mu += zc[c]; }
    mu *= 0.125f;
    float var = 0.f;
#pragma unroll
    for (int c = 0; c < 8; c++) { float d = zc[c] - mu; var = fmaf(d, d, var); }
    var *= 0.125f;
    float rinv = 1.0f / sqrtf(var + LN_EPS);

    if (lane == 0) {
        float o[8];
#pragma unroll
        for (int c = 0; c < 8; c++) o[c] = (zc[c] - mu) * rinv * g[c] + b[c];
        *(float4*)(z + (size_t)tok * 8)     = make_float4(o[0], o[1], o[2], o[3]);
        *(float4*)(z + (size_t)tok * 8 + 4) = make_float4(o[4], o[5], o[6], o[7]);
    }
}

// ---------------- argmin over codebook (broadcast-LDS, register tokens) ----------
#define CHUNK 512
__global__ __launch_bounds__(256) void argmin_kernel(
    int tok_base, const float* __restrict__ emb, const float* __restrict__ z)
{
    __shared__ float se[CHUNK * 8];
    __shared__ float ss[CHUNK];

    int tid  = threadIdx.x;
    int warp = tid >> 5, lane = tid & 31;
    int c0   = blockIdx.x * CHUNK;
    int tok0 = tok_base + blockIdx.y * 1024 + warp * 128 + lane * 4;

    const float4* src = (const float4*)(emb + (size_t)c0 * 8);
#pragma unroll
    for (int u = 0; u < 4; u++) ((float4*)se)[tid + 256 * u] = src[tid + 256 * u];
    __syncthreads();
#pragma unroll
    for (int u = 0; u < 2; u++) {
        int c = tid + 256 * u;
        const float* e = se + c * 8;
        float s = e[0] * e[0];
#pragma unroll
        for (int j = 1; j < 8; j++) s = fmaf(e[j], e[j], s);
        ss[c] = s;
    }
    __syncthreads();

    float zr[4][8], sz2[4];
#pragma unroll
    for (int t = 0; t < 4; t++) {
        float4 a = *(const float4*)(z + (size_t)(tok0 + t) * 8);
        float4 b = *(const float4*)(z + (size_t)(tok0 + t) * 8 + 4);
        zr[t][0] = a.x; zr[t][1] = a.y; zr[t][2] = a.z; zr[t][3] = a.w;
        zr[t][4] = b.x; zr[t][5] = b.y; zr[t][6] = b.z; zr[t][7] = b.w;
        float s = a.x * a.x;
        s = fmaf(a.y, a.y, s); s = fmaf(a.z, a.z, s); s = fmaf(a.w, a.w, s);
        s = fmaf(b.x, b.x, s); s = fmaf(b.y, b.y, s);
        s = fmaf(b.z, b.z, s); s = fmaf(b.w, b.w, s);
        sz2[t] = s;
    }

    float bestd[4];
    int   besti[4];
#pragma unroll
    for (int t = 0; t < 4; t++) { bestd[t] = __int_as_float(0x7f800000); besti[t] = 0; }

#pragma unroll 2
    for (int c = 0; c < CHUNK; c++) {
        float4 ea = *(const float4*)(se + c * 8);
        float4 eb = *(const float4*)(se + c * 8 + 4);
        float ssc = ss[c];
#pragma unroll
        for (int t = 0; t < 4; t++) {
            float dot = zr[t][0] * ea.x;
            dot = fmaf(zr[t][1], ea.y, dot);
            dot = fmaf(zr[t][2], ea.z, dot);
            dot = fmaf(zr[t][3], ea.w, dot);
            dot = fmaf(zr[t][4], eb.x, dot);
            dot = fmaf(zr[t][5], eb.y, dot);
            dot = fmaf(zr[t][6], eb.z, dot);
            dot = fmaf(zr[t][7], eb.w, dot);
            float d = (sz2[t] - 2.0f * dot) + ssc;
            if (d < bestd[t]) { bestd[t] = d; besti[t] = c0 + c; }
        }
    }

#pragma unroll
    for (int t = 0; t < 4; t++) {
        unsigned int m = __float_as_uint(bestd[t]);
        m = ((int)m < 0) ? ~m : (m | 0x80000000u);
        unsigned long long key = ((unsigned long long)m << 32) | (unsigned)besti[t];
        atomicMin(&g_key[tok0 + t], key);
    }
}

// ---------------- hq = relu(emb @ W1_out + b1) -> bf16 hi/lo split ----------------
__global__ void proj_out1(const float* __restrict__ emb,
                          const float* __restrict__ W1o,
                          const float* __restrict__ b1o)
{
    int i = blockIdx.x * 256 + threadIdx.x;
    int k = i >> 9, e = i & 511;
    const float* er = emb + (size_t)k * 8;
    float acc = er[0] * W1o[e];
#pragma unroll
    for (int c = 1; c < 8; c++) acc = fmaf(er[c], W1o[c * 512 + e], acc);
    float x = fmaxf(acc + b1o[e], 0.f);
    __nv_bfloat16 hi = __float2bfloat16(x);
    g_hq_hi[i] = hi;
    g_hq_lo[i] = __float2bfloat16(x - __bfloat162float(hi));
}

// ---------------- W2_out fp32 -> bf16 hi/lo split ----------------
__global__ void split_w2(const float* __restrict__ W)
{
    int i = blockIdx.x * 256 + threadIdx.x;
    float x = W[i];
    __nv_bfloat16 hi = __float2bfloat16(x);
    g_w2_hi[i] = hi;
    g_w2_lo[i] = __float2bfloat16(x - __bfloat162float(hi));
}

// ---------------- tensor-core table GEMM (bf16 3-term split, prefetched) --------
#define AST 40
#define BST 136

__global__ __launch_bounds__(256, 1) void hmma_tbl(
    const float* __restrict__ bias, float* __restrict__ C)
{
    __shared__ __align__(16) __nv_bfloat16 sAhi[128 * AST];
    __shared__ __align__(16) __nv_bfloat16 sAlo[128 * AST];
    __shared__ __align__(16) __nv_bfloat16 sBhi[32 * BST];
    __shared__ __align__(16) __nv_bfloat16 sBlo[32 * BST];

    int tid = threadIdx.x, lane = tid & 31, warp = tid >> 5;
    int wm = warp >> 2, wn = warp & 3;
    int crow = blockIdx.y * 128, ccol = blockIdx.x * 128;

    const __nv_bfloat16* Ahi = g_hq_hi + (size_t)crow * 512;
    const __nv_bfloat16* Alo = g_hq_lo + (size_t)crow * 512;

    float acc[4][4][4];
#pragma unroll
    for (int mi = 0; mi < 4; mi++)
#pragma unroll
        for (int ni = 0; ni < 4; ni++)
#pragma unroll
            for (int r = 0; r < 4; r++) acc[mi][ni][r] = 0.f;

    // staging coords (2 per thread)
    int rA[2], cA[2], rB[2], cB[2];
#pragma unroll
    for (int u = 0; u < 2; u++) {
        int e = tid + u * 256;
        rA[u] = e >> 2;  cA[u] = (e & 3) * 8;
        rB[u] = e >> 4;  cB[u] = (e & 15) * 8;
    }

    uint4 pAh[2], pAl[2], pBh[2], pBl[2];
#pragma unroll
    for (int u = 0; u < 2; u++) {   // prefetch kt = 0
        pAh[u] = *(const uint4*)&Ahi[(size_t)rA[u] * 512 + cA[u]];
        pAl[u] = *(const uint4*)&Alo[(size_t)rA[u] * 512 + cA[u]];
        pBh[u] = *(const uint4*)&g_w2_hi[(size_t)rB[u] * 512 + ccol + cB[u]];
        pBl[u] = *(const uint4*)&g_w2_lo[(size_t)rB[u] * 512 + ccol + cB[u]];
    }

    for (int kt = 0; kt < 16; kt++) {
        if (kt) __syncthreads();
#pragma unroll
        for (int u = 0; u < 2; u++) {
            *(uint4*)&sAhi[rA[u] * AST + cA[u]] = pAh[u];
            *(uint4*)&sAlo[rA[u] * AST + cA[u]] = pAl[u];
            *(uint4*)&sBhi[rB[u] * BST + cB[u]] = pBh[u];
            *(uint4*)&sBlo[rB[u] * BST + cB[u]] = pBl[u];
        }
        __syncthreads();

        if (kt + 1 < 16) {          // prefetch next tile
            int k0 = (kt + 1) * 32;
#pragma unroll
            for (int u = 0; u < 2; u++) {
                pAh[u] = *(const uint4*)&Ahi[(size_t)rA[u] * 512 + k0 + cA[u]];
                pAl[u] = *(const uint4*)&Alo[(size_t)rA[u] * 512 + k0 + cA[u]];
                pBh[u] = *(const uint4*)&g_w2_hi[(size_t)(k0 + rB[u]) * 512 + ccol + cB[u]];
                pBl[u] = *(const uint4*)&g_w2_lo[(size_t)(k0 + rB[u]) * 512 + ccol + cB[u]];
            }
        }

#pragma unroll
        for (int ks = 0; ks < 2; ks++) {
            int kk = ks * 16;
            uint32_t afh[4][4], afl[4][4], bfh[4][2], bfl[4][2];
#pragma unroll
            for (int mi = 0; mi < 4; mi++) {
                int row = wm * 64 + mi * 16 + (lane & 15);
                int col = kk + ((lane >> 4) << 3);
                LDSM_X4(afh[mi][0], afh[mi][1], afh[mi][2], afh[mi][3],
                        smem_u32(&sAhi[row * AST + col]));
                LDSM_X4(afl[mi][0], afl[mi][1], afl[mi][2], afl[mi][3],
                        smem_u32(&sAlo[row * AST + col]));
            }
#pragma unroll
            for (int nq = 0; nq < 2; nq++) {
                int krow = kk + (lane & 15);
                int col  = wn * 32 + nq * 16 + ((lane >> 4) << 3);
                uint32_t r0, r1, r2, r3;
                LDSM_X4T(r0, r1, r2, r3, smem_u32(&sBhi[krow * BST + col]));
                bfh[nq * 2][0] = r0; bfh[nq * 2][1] = r1;
                bfh[nq * 2 + 1][0] = r2; bfh[nq * 2 + 1][1] = r3;
                LDSM_X4T(r0, r1, r2, r3, smem_u32(&sBlo[krow * BST + col]));
                bfl[nq * 2][0] = r0; bfl[nq * 2][1] = r1;
                bfl[nq * 2 + 1][0] = r2; bfl[nq * 2 + 1][1] = r3;
            }
#pragma unroll
            for (int mi = 0; mi < 4; mi++)
#pragma unroll
                for (int ni = 0; ni < 4; ni++) {
                    MMA_BF16(acc[mi][ni], afh[mi], bfh[ni]);
                    MMA_BF16(acc[mi][ni], afh[mi], bfl[ni]);
                    MMA_BF16(acc[mi][ni], afl[mi], bfh[ni]);
                }
        }
    }

    int gr = lane >> 2, gc = (lane & 3) * 2;
#pragma unroll
    for (int mi = 0; mi < 4; mi++)
#pragma unroll
        for (int ni = 0; ni < 4; ni++) {
            int rr = crow + wm * 64 + mi * 16 + gr;
            int cc = ccol + wn * 32 + ni * 8 + gc;
            float b0 = bias[cc], b1 = bias[cc + 1];
            C[(size_t)rr * 512 + cc]           = acc[mi][ni][0] + b0;
            C[(size_t)rr * 512 + cc + 1]       = acc[mi][ni][1] + b1;
            C[(size_t)(rr + 8) * 512 + cc]     = acc[mi][ni][2] + b0;
            C[(size_t)(rr + 8) * 512 + cc + 1] = acc[mi][ni][3] + b1;
        }
}

// ---------------- row LayerNorm over E=512 — one warp per row ----------------
__global__ __launch_bounds__(256) void ln_rows(
    const float* __restrict__ x, const float* __restrict__ g,
    const float* __restrict__ b, float* __restrict__ y)
{
    int warp = (blockIdx.x * 256 + threadIdx.x) >> 5;
    int lane = threadIdx.x & 31;
    const float* r = x + (size_t)warp * 512;

    float4 v[4];
    float s = 0.f;
#pragma unroll
    for (int i = 0; i < 4; i++) {
        v[i] = ((const float4*)r)[lane + 32 * i];
        s += v[i].x + v[i].y + v[i].z + v[i].w;
    }
#pragma unroll
    for (int off = 16; off > 0; off >>= 1) s += __shfl_xor_sync(0xffffffffu, s, off);
    float mu = s * (1.0f / 512.0f);

    float s2 = 0.f;
#pragma unroll
    for (int i = 0; i < 4; i++) {
        float dx;
        dx = v[i].x - mu; s2 = fmaf(dx, dx, s2);
        dx = v[i].y - mu; s2 = fmaf(dx, dx, s2);
        dx = v[i].z - mu; s2 = fmaf(dx, dx, s2);
        dx = v[i].w - mu; s2 = fmaf(dx, dx, s2);
    }
#pragma unroll
    for (int off = 16; off > 0; off >>= 1) s2 += __shfl_xor_sync(0xffffffffu, s2, off);
    float var = s2 * (1.0f / 512.0f);
    float inv = 1.0f / sqrtf(var + LN_EPS);

#pragma unroll
    for (int i = 0; i < 4; i++) {
        int e = 4 * (lane + 32 * i);
        float4 gg = *(const float4*)(g + e);
        float4 bb = *(const float4*)(b + e);
        float4 o;
        o.x = (v[i].x - mu) * inv * gg.x + bb.x;
        o.y = (v[i].y - mu) * inv * gg.y + bb.y;
        o.z = (v[i].z - mu) * inv * gg.z + bb.z;
        o.w = (v[i].w - mu) * inv * gg.w + bb.w;
        ((float4*)(y + (size_t)warp * 512))[lane + 32 * i] = o;
    }
}

// ---------------- gather: q rows, idx (as float), one-hot scatter ----------------
__global__ void gather_out(float* __restrict__ outq, float* __restrict__ outidx,
                           float* __restrict__ outenc)
{
    int tok = blockIdx.x;
    int k = (int)(g_key[tok] & 0xFFFFFFFFull);
    int t = threadIdx.x;
    float4 v = ((const float4*)(g_tbl + (size_t)k * 512))[t];
    ((float4*)(outq + (size_t)tok * 512))[t] = v;
    if (t == 0) {
        if (outidx) outidx[tok] = (float)k;
        if (outenc) outenc[(size_t)tok * K_CODES + k] = 1.0f;
    }
}

// ---------------- launch ----------------
extern "C" void kernel_launch(void* const* d_in, const int* in_sizes, int n_in,
                              void* d_out, int out_size)
{
    const float* features = (const float*)d_in[0];
    const float* W1_in    = (const float*)d_in[1];
    const float* b1_in    = (const float*)d_in[2];
    const float* W2_in    = (const float*)d_in[3];
    const float* b2_in    = (const float*)d_in[4];
    const float* ln_in_g  = (const float*)d_in[5];
    const float* ln_in_b  = (const float*)d_in[6];
    const float* emb      = (const float*)d_in[7];
    const float* W1_out   = (const float*)d_in[8];
    const float* b1_out   = (const float*)d_in[9];
    const float* W2_out   = (const float*)d_in[10];
    const float* b2_out   = (const float*)d_in[11];
    const float* ln_out_g = (const float*)d_in[12];
    const float* ln_out_b = (const float*)d_in[13];

    float* out = (float*)d_out;
    const long long q_elems   = (long long)N_TOK * E_DIM;
    const long long idx_elems = N_TOK;
    const long long enc_elems = (long long)N_TOK * K_CODES;
    float* outq   = out;
    float* outidx = nullptr;
    float* outenc = nullptr;
    if ((long long)out_size >= q_elems + idx_elems + enc_elems) {
        outidx = out + q_elems;
        outenc = out + q_elems + idx_elems;
    } else if ((long long)out_size >= q_elems + idx_elems) {
        outidx = out + q_elems;
    }

    float *p_h, *p_z, *p_tpre, *p_tbl;
    __nv_bfloat16 *p_fhi, *p_fmi, *p_flo, *p_w1hi, *p_w1mi, *p_w1lo;
    void* p_key;
    cudaGetSymbolAddress((void**)&p_h,    g_h);
    cudaGetSymbolAddress((void**)&p_z,    g_z);
    cudaGetSymbolAddress((void**)&p_tpre, g_tpre);
    cudaGetSymbolAddress((void**)&p_tbl,  g_tbl);
    cudaGetSymbolAddress((void**)&p_fhi,  g_fhi);
    cudaGetSymbolAddress((void**)&p_fmi,  g_fmi);
    cudaGetSymbolAddress((void**)&p_flo,  g_flo);
    cudaGetSymbolAddress((void**)&p_w1hi, g_w1hi);
    cudaGetSymbolAddress((void**)&p_w1mi, g_w1mi);
    cudaGetSymbolAddress((void**)&p_w1lo, g_w1lo);
    cudaGetSymbolAddress(&p_key, g_key);

    // streams: B = codebook table, C = encodings memset, D = hmma token pipeline
    static cudaStream_t sB = nullptr, sC = nullptr, sD = nullptr;
    static cudaEvent_t evF = nullptr, evB = nullptr, evC = nullptr, evD = nullptr,
                       evK = nullptr;
    if (!sB) {
        cudaStreamCreateWithFlags(&sB, cudaStreamNonBlocking);
        cudaStreamCreateWithFlags(&sC, cudaStreamNonBlocking);
        cudaStreamCreateWithFlags(&sD, cudaStreamNonBlocking);
        cudaEventCreateWithFlags(&evF, cudaEventDisableTiming);
        cudaEventCreateWithFlags(&evB, cudaEventDisableTiming);
        cudaEventCreateWithFlags(&evC, cudaEventDisableTiming);
        cudaEventCreateWithFlags(&evD, cudaEventDisableTiming);
        cudaEventCreateWithFlags(&evK, cudaEventDisableTiming);
    }

    cudaEventRecord(evF, 0);
    cudaStreamWaitEvent(sB, evF, 0);
    cudaStreamWaitEvent(sC, evF, 0);
    cudaStreamWaitEvent(sD, evF, 0);

    // ---- stream C: encodings memset (pure DRAM, hides under compute) ----
    if (outenc)
        cudaMemsetAsync(outenc, 0, (size_t)enc_elems * sizeof(float), sC);
    cudaEventRecord(evC, sC);

    // ---- stream B: codebook output table (validated bf16 tensor path) ----
    split_w2<<<(E_DIM * E_DIM) / 256, 256, 0, sB>>>(W2_out);
    proj_out1<<<(K_CODES * E_DIM) / 256, 256, 0, sB>>>(emb, W1_out, b1_out);
    dim3 g2(E_DIM / 128, K_CODES / 128);
    hmma_tbl<<<g2, 256, 0, sB>>>(b2_out, p_tpre);
    ln_rows<<<K_CODES / 8, 256, 0, sB>>>(p_tpre, ln_out_g, ln_out_b, p_tbl);
    cudaEventRecord(evB, sB);

    // ---- stream 0: g_key init (gates both argmin halves) ----
    cudaMemsetAsync(p_key, 0xFF, N_TOK * sizeof(unsigned long long), 0);
    cudaEventRecord(evK, 0);

    // ---- stream D: bf16 token pipeline (rows M_SPLIT..N_TOK) ----
    {
        const size_t off = (size_t)M_SPLIT * E_DIM;
        split3<<<((N_TOK - M_SPLIT) * E_DIM) / 256, 256, 0, sD>>>(
            features + off, p_fhi + off, p_fmi + off, p_flo + off);
        split3<<<(E_DIM * E_DIM) / 256, 256, 0, sD>>>(
            W1_in, p_w1hi, p_w1mi, p_w1lo);
        dim3 gd(E_DIM / 128, (N_TOK - M_SPLIT) / 128);
        hmma3_gemm1<<<gd, 256, 0, sD>>>(M_SPLIT, b1_in, p_h);
        gemm2_ln<<<(N_TOK - M_SPLIT) / 8, 256, 0, sD>>>(
            M_SPLIT, p_h, W2_in, b2_in, ln_in_g, ln_in_b, p_z);
        cudaStreamWaitEvent(sD, evK, 0);
        argmin_kernel<<<dim3(K_CODES / CHUNK, (N_TOK - M_SPLIT) / 1024), 256, 0, sD>>>(
            M_SPLIT, emb, p_z);
    }
    cudaEventRecord(evD, sD);

    // ---- stream 0: fp32 token pipeline (rows 0..M_SPLIT) ----
    dim3 g1(E_DIM / 128, M_SPLIT / 128);
    sgemm_bias<1><<<g1, 256>>>(M_SPLIT, E_DIM, E_DIM, features, W1_in, b1_in, p_h);
    gemm2_ln<<<M_SPLIT / 8, 256>>>(0, p_h, W2_in, b2_in, ln_in_g, ln_in_b, p_z);
    argmin_kernel<<<dim3(K_CODES / CHUNK, M_SPLIT / 1024), 256>>>(0, emb, p_z);

    // join + final gather
    cudaStreamWaitEvent(0, evD, 0);
    cudaStreamWaitEvent(0, evB, 0);
    cudaStreamWaitEvent(0, evC, 0);
    gather_out<<<N_TOK, 128>>>(outq, outidx, outenc);
}

// round 14
// speedup vs baseline: 1.0761x; 1.0013x over previous
#include <cuda_runtime.h>
#include <cuda_bf16.h>
#include <math.h>
#include <stdint.h>

#define N_TOK   16384
#define E_DIM   512
#define C_DIM   8
#define K_CODES 8192
#define LN_EPS  1e-5f
#define M_SPLIT 8192   // rows [0,M_SPLIT) fp32, [M_SPLIT,N_TOK) bf16-hmma

// ---------------- scratch (device globals: no allocation allowed) ----------------
__device__ float g_h[N_TOK * E_DIM];        // relu(features@W1_in+b1)   32MB
__device__ float g_z[N_TOK * C_DIM];        // layernormed code-space
__device__ unsigned long long g_key[N_TOK]; // packed (dist,idx) argmin keys
__device__ float g_tpre[K_CODES * E_DIM];   // pre-LN table              16MB
__device__ float g_tbl[K_CODES * E_DIM];    // final per-code output     16MB

// bf16 split operands
__device__ __nv_bfloat16 g_hq_hi[K_CODES * E_DIM];
__device__ __nv_bfloat16 g_hq_lo[K_CODES * E_DIM];
__device__ __nv_bfloat16 g_w2_hi[E_DIM * E_DIM];
__device__ __nv_bfloat16 g_w2_lo[E_DIM * E_DIM];
__device__ __nv_bfloat16 g_fhi[N_TOK * E_DIM];   // features 3-way split (2nd half used)
__device__ __nv_bfloat16 g_fmi[N_TOK * E_DIM];
__device__ __nv_bfloat16 g_flo[N_TOK * E_DIM];
__device__ __nv_bfloat16 g_w1hi[E_DIM * E_DIM];  // W1_in split [k][n]
__device__ __nv_bfloat16 g_w1mi[E_DIM * E_DIM];
__device__ __nv_bfloat16 g_w1lo[E_DIM * E_DIM];

// ---------------- common HMMA helpers ----------------
__device__ __forceinline__ uint32_t smem_u32(const void* p) {
    return (uint32_t)__cvta_generic_to_shared(p);
}
#define LDSM_X4(r0,r1,r2,r3,addr) \
    asm volatile("ldmatrix.sync.aligned.m8n8.x4.shared.b16 {%0,%1,%2,%3},[%4];" \
        : "=r"(r0),"=r"(r1),"=r"(r2),"=r"(r3) : "r"(addr))
#define LDSM_X4T(r0,r1,r2,r3,addr) \
    asm volatile("ldmatrix.sync.aligned.m8n8.x4.trans.shared.b16 {%0,%1,%2,%3},[%4];" \
        : "=r"(r0),"=r"(r1),"=r"(r2),"=r"(r3) : "r"(addr))
#define MMA_BF16(d, a, b) \
    asm volatile("mma.sync.aligned.m16n8k16.row.col.f32.bf16.bf16.f32 " \
        "{%0,%1,%2,%3},{%4,%5,%6,%7},{%8,%9},{%0,%1,%2,%3};" \
        : "+f"(d[0]),"+f"(d[1]),"+f"(d[2]),"+f"(d[3]) \
        : "r"(a[0]),"r"(a[1]),"r"(a[2]),"r"(a[3]),"r"(b[0]),"r"(b[1]))

// ---------------- fp32 SGEMM with register prefetch ----------------
// Same arithmetic/order as the validated kernel; next tile's LDGs issue before
// the FFMA block so load latency hides under compute.
template <int DO_RELU>
__global__ __launch_bounds__(256) void sgemm_bias(
    int M, int Nn, int Kd,
    const float* __restrict__ A, const float* __restrict__ B,
    const float* __restrict__ bias, float* __restrict__ C)
{
    const int BM = 128, BN = 128, BK = 16, TM = 8, TN = 8;
    __shared__ float As[BK][BM];
    __shared__ float Bs[BK][BN];

    int tid  = threadIdx.x;
    int crow = blockIdx.y * BM;
    int ccol = blockIdx.x * BN;

    int aRow = tid >> 2;
    int aCol = (tid & 3) << 2;
    int bRow = tid >> 5;
    int bCol = (tid & 31) << 2;

    int trow = (tid >> 4) << 3;
    int tcol = (tid & 15) << 3;

    const float* Ap = A + (size_t)crow * Kd;
    const float* Bp = B + ccol;

    float acc[TM][TN];
#pragma unroll
    for (int i = 0; i < TM; i++)
#pragma unroll
        for (int j = 0; j < TN; j++) acc[i][j] = 0.f;

    float4 pA[2], pB[2];
#pragma unroll
    for (int r = 0; r < 2; r++) {     // prefetch k0 = 0
        pA[r] = *(const float4*)(Ap + (size_t)(aRow + 64 * r) * Kd + aCol);
        pB[r] = *(const float4*)(Bp + (size_t)(bRow + 8 * r) * Nn + bCol);
    }

    int nkt = Kd / BK;
    for (int kt = 0; kt < nkt; kt++) {
        if (kt) __syncthreads();
#pragma unroll
        for (int r = 0; r < 2; r++) {
            As[aCol + 0][aRow + 64 * r] = pA[r].x;
            As[aCol + 1][aRow + 64 * r] = pA[r].y;
            As[aCol + 2][aRow + 64 * r] = pA[r].z;
            As[aCol + 3][aRow + 64 * r] = pA[r].w;
            *(float4*)(&Bs[bRow + 8 * r][bCol]) = pB[r];
        }
        __syncthreads();

        if (kt + 1 < nkt) {            // prefetch next tile
            int k0 = (kt + 1) * BK;
#pragma unroll
            for (int r = 0; r < 2; r++) {
                pA[r] = *(const float4*)(Ap + (size_t)(aRow + 64 * r) * Kd + k0 + aCol);
                pB[r] = *(const float4*)(Bp + (size_t)(k0 + bRow + 8 * r) * Nn + bCol);
            }
        }

#pragma unroll
        for (int k = 0; k < BK; k++) {
            float regM[TM], regN[TN];
            *(float4*)&regM[0] = *(const float4*)&As[k][trow];
            *(float4*)&regM[4] = *(const float4*)&As[k][trow + 4];
            *(float4*)&regN[0] = *(const float4*)&Bs[k][tcol];
            *(float4*)&regN[4] = *(const float4*)&Bs[k][tcol + 4];
#pragma unroll
            for (int i = 0; i < TM; i++)
#pragma unroll
                for (int j = 0; j < TN; j++)
                    acc[i][j] = fmaf(regM[i], regN[j], acc[i][j]);
        }
    }

#pragma unroll
    for (int i = 0; i < TM; i++) {
#pragma unroll
        for (int j4 = 0; j4 < TN; j4 += 4) {
            float4 bv = *(const float4*)(bias + ccol + tcol + j4);
            float4 o;
            o.x = acc[i][j4 + 0] + bv.x;
            o.y = acc[i][j4 + 1] + bv.y;
            o.z = acc[i][j4 + 2] + bv.z;
            o.w = acc[i][j4 + 3] + bv.w;
            if (DO_RELU) {
                o.x = fmaxf(o.x, 0.f); o.y = fmaxf(o.y, 0.f);
                o.z = fmaxf(o.z, 0.f); o.w = fmaxf(o.w, 0.f);
            }
            *(float4*)(C + (size_t)(crow + trow + i) * Nn + ccol + tcol + j4) = o;
        }
    }
}

// ---------------- 3-way bf16 split ----------------
__global__ void split3(const float* __restrict__ x,
                       __nv_bfloat16* __restrict__ hi,
                       __nv_bfloat16* __restrict__ mi,
                       __nv_bfloat16* __restrict__ lo)
{
    int i = blockIdx.x * 256 + threadIdx.x;
    float v = x[i];
    __nv_bfloat16 h = __float2bfloat16(v);
    float r = v - __bfloat162float(h);
    __nv_bfloat16 m = __float2bfloat16(r);
    float r2 = r - __bfloat162float(m);
    hi[i] = h; mi[i] = m; lo[i] = __float2bfloat16(r2);
}

// ---------------- GEMM1 (rows >= M_SPLIT): bf16 6-product HMMA, prefetched ------
#define A3ST 24
#define B3ST 136

__global__ __launch_bounds__(256, 1) void hmma3_gemm1(
    int row0, const float* __restrict__ bias, float* __restrict__ C)
{
    __shared__ __align__(16) __nv_bfloat16 sAh[128 * A3ST];
    __shared__ __align__(16) __nv_bfloat16 sAm[128 * A3ST];
    __shared__ __align__(16) __nv_bfloat16 sAl[128 * A3ST];
    __shared__ __align__(16) __nv_bfloat16 sBh[16 * B3ST];
    __shared__ __align__(16) __nv_bfloat16 sBm[16 * B3ST];
    __shared__ __align__(16) __nv_bfloat16 sBl[16 * B3ST];

    int tid = threadIdx.x, lane = tid & 31, warp = tid >> 5;
    int wm = warp >> 2, wn = warp & 3;
    int crow = row0 + blockIdx.y * 128, ccol = blockIdx.x * 128;

    int ra = tid >> 1, c8 = (tid & 1) * 8;
    int rb = tid >> 4, cb = (tid & 15) * 8;

    float acc[4][4][4];
#pragma unroll
    for (int mi = 0; mi < 4; mi++)
#pragma unroll
        for (int ni = 0; ni < 4; ni++)
#pragma unroll
            for (int r = 0; r < 4; r++) acc[mi][ni][r] = 0.f;

    uint4 pA0, pA1, pA2, pB0, pB1, pB2;
    {
        size_t go = (size_t)(crow + ra) * 512 + c8;
        pA0 = *(const uint4*)&g_fhi[go];
        pA1 = *(const uint4*)&g_fmi[go];
        pA2 = *(const uint4*)&g_flo[go];
        size_t gb = (size_t)rb * 512 + ccol + cb;
        pB0 = *(const uint4*)&g_w1hi[gb];
        pB1 = *(const uint4*)&g_w1mi[gb];
        pB2 = *(const uint4*)&g_w1lo[gb];
    }

    for (int kt = 0; kt < 32; kt++) {
        if (kt) __syncthreads();
        *(uint4*)&sAh[ra * A3ST + c8] = pA0;
        *(uint4*)&sAm[ra * A3ST + c8] = pA1;
        *(uint4*)&sAl[ra * A3ST + c8] = pA2;
        *(uint4*)&sBh[rb * B3ST + cb] = pB0;
        *(uint4*)&sBm[rb * B3ST + cb] = pB1;
        *(uint4*)&sBl[rb * B3ST + cb] = pB2;
        __syncthreads();

        if (kt + 1 < 32) {
            int k0 = (kt + 1) * 16;
            size_t go = (size_t)(crow + ra) * 512 + k0 + c8;
            pA0 = *(const uint4*)&g_fhi[go];
            pA1 = *(const uint4*)&g_fmi[go];
            pA2 = *(const uint4*)&g_flo[go];
            size_t gb = (size_t)(k0 + rb) * 512 + ccol + cb;
            pB0 = *(const uint4*)&g_w1hi[gb];
            pB1 = *(const uint4*)&g_w1mi[gb];
            pB2 = *(const uint4*)&g_w1lo[gb];
        }

        uint32_t afh[4][4], afm[4][4], afl[4][4];
#pragma unroll
        for (int mi = 0; mi < 4; mi++) {
            int row = wm * 64 + mi * 16 + (lane & 15);
            int col = (lane >> 4) << 3;
            LDSM_X4(afh[mi][0], afh[mi][1], afh[mi][2], afh[mi][3],
                    smem_u32(&sAh[row * A3ST + col]));
            LDSM_X4(afm[mi][0], afm[mi][1], afm[mi][2], afm[mi][3],
                    smem_u32(&sAm[row * A3ST + col]));
            LDSM_X4(afl[mi][0], afl[mi][1], afl[mi][2], afl[mi][3],
                    smem_u32(&sAl[row * A3ST + col]));
        }
        uint32_t bfr[4][2];
#pragma unroll
        for (int nq = 0; nq < 2; nq++) {
            int krow = lane & 15;
            int col  = wn * 32 + nq * 16 + ((lane >> 4) << 3);
            uint32_t r0, r1, r2, r3;
            LDSM_X4T(r0, r1, r2, r3, smem_u32(&sBh[krow * B3ST + col]));
            bfr[nq * 2][0] = r0; bfr[nq * 2][1] = r1;
            bfr[nq * 2 + 1][0] = r2; bfr[nq * 2 + 1][1] = r3;
        }
#pragma unroll
        for (int mi = 0; mi < 4; mi++)
#pragma unroll
            for (int ni = 0; ni < 4; ni++) {
                MMA_BF16(acc[mi][ni], afh[mi], bfr[ni]);
                MMA_BF16(acc[mi][ni], afm[mi], bfr[ni]);
                MMA_BF16(acc[mi][ni], afl[mi], bfr[ni]);
            }
#pragma unroll
        for (int nq = 0; nq < 2; nq++) {
            int krow = lane & 15;
            int col  = wn * 32 + nq * 16 + ((lane >> 4) << 3);
            uint32_t r0, r1, r2, r3;
            LDSM_X4T(r0, r1, r2, r3, smem_u32(&sBm[krow * B3ST + col]));
            bfr[nq * 2][0] = r0; bfr[nq * 2][1] = r1;
            bfr[nq * 2 + 1][0] = r2; bfr[nq * 2 + 1][1] = r3;
        }
#pragma unroll
        for (int mi = 0; mi < 4; mi++)
#pragma unroll
            for (int ni = 0; ni < 4; ni++) {
                MMA_BF16(acc[mi][ni], afh[mi], bfr[ni]);
                MMA_BF16(acc[mi][ni], afm[mi], bfr[ni]);
            }
#pragma unroll
        for (int nq = 0; nq < 2; nq++) {
            int krow = lane & 15;
            int col  = wn * 32 + nq * 16 + ((lane >> 4) << 3);
            uint32_t r0, r1, r2, r3;
            LDSM_X4T(r0, r1, r2, r3, smem_u32(&sBl[krow * B3ST + col]));
            bfr[nq * 2][0] = r0; bfr[nq * 2][1] = r1;
            bfr[nq * 2 + 1][0] = r2; bfr[nq * 2 + 1][1] = r3;
        }
#pragma unroll
        for (int mi = 0; mi < 4; mi++)
#pragma unroll
            for (int ni = 0; ni < 4; ni++)
                MMA_BF16(acc[mi][ni], afh[mi], bfr[ni]);
    }

    int gr = lane >> 2, gc = (lane & 3) * 2;
#pragma unroll
    for (int mi = 0; mi < 4; mi++)
#pragma unroll
        for (int ni = 0; ni < 4; ni++) {
            int rr = crow + wm * 64 + mi * 16 + gr;
            int cc = ccol + wn * 32 + ni * 8 + gc;
            float b0 = bias[cc], b1 = bias[cc + 1];
            C[(size_t)rr * 512 + cc]           = fmaxf(acc[mi][ni][0] + b0, 0.f);
            C[(size_t)rr * 512 + cc + 1]       = fmaxf(acc[mi][ni][1] + b1, 0.f);
            C[(size_t)(rr + 8) * 512 + cc]     = fmaxf(acc[mi][ni][2] + b0, 0.f);
            C[(size_t)(rr + 8) * 512 + cc + 1] = fmaxf(acc[mi][ni][3] + b1, 0.f);
        }
}

// ---------------- z = LN(h @ W2_in + b2)  — one warp per token ----------------
__global__ __launch_bounds__(256) void gemm2_ln(
    int tok0, const float* __restrict__ h, const float* __restrict__ W2,
    const float* __restrict__ b2, const float* __restrict__ g,
    const float* __restrict__ b, float* __restrict__ z)
{
    __shared__ float w2t[C_DIM * E_DIM];
    int tid = threadIdx.x;
    for (int i = tid; i < C_DIM * E_DIM; i += 256) {
        int c = i >> 9, e = i & 511;
        w2t[i] = W2[e * C_DIM + c];
    }
    __syncthreads();

    int warp = tid >> 5, lane = tid & 31;
    int tok = tok0 + blockIdx.x * 8 + warp;
    const float* hr = h + (size_t)tok * E_DIM;

    float acc[8] = {0.f, 0.f, 0.f, 0.f, 0.f, 0.f, 0.f, 0.f};
#pragma unroll
    for (int i = 0; i < 16; i++) {
        int e = i * 32 + lane;
        float hv = hr[e];
#pragma unroll
        for (int c = 0; c < 8; c++)
            acc[c] = fmaf(hv, w2t[c * 512 + e], acc[c]);
    }
#pragma unroll
    for (int c = 0; c < 8; c++)
#pragma unroll
        for (int off = 16; off > 0; off >>= 1)
            acc[c] += __shfl_xor_sync(0xffffffffu, acc[c], off);

    float zc[8], mu = 0.f;
#pragma unroll
    for (int c = 0; c < 8; c++) { zc[c] = acc[c] + b2[c]; mu += zc[c]; }
    mu *= 0.125f;
    float var = 0.f;
#pragma unroll
    for (int c = 0; c < 8; c++) { float d = zc[c] - mu; var = fmaf(d, d, var); }
    var *= 0.125f;
    float rinv = 1.0f / sqrtf(var + LN_EPS);

    if (lane == 0) {
        float o[8];
#pragma unroll
        for (int c = 0; c < 8; c++) o[c] = (zc[c] - mu) * rinv * g[c] + b[c];
        *(float4*)(z + (size_t)tok * 8)     = make_float4(o[0], o[1], o[2], o[3]);
        *(float4*)(z + (size_t)tok * 8 + 4) = make_float4(o[4], o[5], o[6], o[7]);
    }
}

// ---------------- argmin over codebook (broadcast-LDS, register tokens) ----------
#define CHUNK 512
__global__ __launch_bounds__(256) void argmin_kernel(
    int tok_base, const float* __restrict__ emb, const float* __restrict__ z)
{
    __shared__ float se[CHUNK * 8];
    __shared__ float ss[CHUNK];

    int tid  = threadIdx.x;
    int warp = tid >> 5, lane = tid & 31;
    int c0   = blockIdx.x * CHUNK;
    int tok0 = tok_base + blockIdx.y * 1024 + warp * 128 + lane * 4;

    const float4* src = (const float4*)(emb + (size_t)c0 * 8);
#pragma unroll
    for (int u = 0; u < 4; u++) ((float4*)se)[tid + 256 * u] = src[tid + 256 * u];
    __syncthreads();
#pragma unroll
    for (int u = 0; u < 2; u++) {
        int c = tid + 256 * u;
        const float* e = se + c * 8;
        float s = e[0] * e[0];
#pragma unroll
        for (int j = 1; j < 8; j++) s = fmaf(e[j], e[j], s);
        ss[c] = s;
    }
    __syncthreads();

    float zr[4][8], sz2[4];
#pragma unroll
    for (int t = 0; t < 4; t++) {
        float4 a = *(const float4*)(z + (size_t)(tok0 + t) * 8);
        float4 b = *(const float4*)(z + (size_t)(tok0 + t) * 8 + 4);
        zr[t][0] = a.x; zr[t][1] = a.y; zr[t][2] = a.z; zr[t][3] = a.w;
        zr[t][4] = b.x; zr[t][5] = b.y; zr[t][6] = b.z; zr[t][7] = b.w;
        float s = a.x * a.x;
        s = fmaf(a.y, a.y, s); s = fmaf(a.z, a.z, s); s = fmaf(a.w, a.w, s);
        s = fmaf(b.x, b.x, s); s = fmaf(b.y, b.y, s);
        s = fmaf(b.z, b.z, s); s = fmaf(b.w, b.w, s);
        sz2[t] = s;
    }

    float bestd[4];
    int   besti[4];
#pragma unroll
    for (int t = 0; t < 4; t++) { bestd[t] = __int_as_float(0x7f800000); besti[t] = 0; }

#pragma unroll 2
    for (int c = 0; c < CHUNK; c++) {
        float4 ea = *(const float4*)(se + c * 8);
        float4 eb = *(const float4*)(se + c * 8 + 4);
        float ssc = ss[c];
#pragma unroll
        for (int t = 0; t < 4; t++) {
            float dot = zr[t][0] * ea.x;
            dot = fmaf(zr[t][1], ea.y, dot);
            dot = fmaf(zr[t][2], ea.z, dot);
            dot = fmaf(zr[t][3], ea.w, dot);
            dot = fmaf(zr[t][4], eb.x, dot);
            dot = fmaf(zr[t][5], eb.y, dot);
            dot = fmaf(zr[t][6], eb.z, dot);
            dot = fmaf(zr[t][7], eb.w, dot);
            float d = (sz2[t] - 2.0f * dot) + ssc;
            if (d < bestd[t]) { bestd[t] = d; besti[t] = c0 + c; }
        }
    }

#pragma unroll
    for (int t = 0; t < 4; t++) {
        unsigned int m = __float_as_uint(bestd[t]);
        m = ((int)m < 0) ? ~m : (m | 0x80000000u);
        unsigned long long key = ((unsigned long long)m << 32) | (unsigned)besti[t];
        atomicMin(&g_key[tok0 + t], key);
    }
}

// ---------------- hq = relu(emb @ W1_out + b1) -> bf16 hi/lo split ----------------
__global__ void proj_out1(const float* __restrict__ emb,
                          const float* __restrict__ W1o,
                          const float* __restrict__ b1o)
{
    int i = blockIdx.x * 256 + threadIdx.x;
    int k = i >> 9, e = i & 511;
    const float* er = emb + (size_t)k * 8;
    float acc = er[0] * W1o[e];
#pragma unroll
    for (int c = 1; c < 8; c++) acc = fmaf(er[c], W1o[c * 512 + e], acc);
    float x = fmaxf(acc + b1o[e], 0.f);
    __nv_bfloat16 hi = __float2bfloat16(x);
    g_hq_hi[i] = hi;
    g_hq_lo[i] = __float2bfloat16(x - __bfloat162float(hi));
}

// ---------------- W2_out fp32 -> bf16 hi/lo split ----------------
__global__ void split_w2(const float* __restrict__ W)
{
    int i = blockIdx.x * 256 + threadIdx.x;
    float x = W[i];
    __nv_bfloat16 hi = __float2bfloat16(x);
    g_w2_hi[i] = hi;
    g_w2_lo[i] = __float2bfloat16(x - __bfloat162float(hi));
}

// ---------------- tensor-core table GEMM (bf16 3-term split, prefetched) --------
#define AST 40
#define BST 136

__global__ __launch_bounds__(256, 1) void hmma_tbl(
    const float* __restrict__ bias, float* __restrict__ C)
{
    __shared__ __align__(16) __nv_bfloat16 sAhi[128 * AST];
    __shared__ __align__(16) __nv_bfloat16 sAlo[128 * AST];
    __shared__ __align__(16) __nv_bfloat16 sBhi[32 * BST];
    __shared__ __align__(16) __nv_bfloat16 sBlo[32 * BST];

    int tid = threadIdx.x, lane = tid & 31, warp = tid >> 5;
    int wm = warp >> 2, wn = warp & 3;
    int crow = blockIdx.y * 128, ccol = blockIdx.x * 128;

    const __nv_bfloat16* Ahi = g_hq_hi + (size_t)crow * 512;
    const __nv_bfloat16* Alo = g_hq_lo + (size_t)crow * 512;

    float acc[4][4][4];
#pragma unroll
    for (int mi = 0; mi < 4; mi++)
#pragma unroll
        for (int ni = 0; ni < 4; ni++)
#pragma unroll
            for (int r = 0; r < 4; r++) acc[mi][ni][r] = 0.f;

    int rA[2], cA[2], rB[2], cB[2];
#pragma unroll
    for (int u = 0; u < 2; u++) {
        int e = tid + u * 256;
        rA[u] = e >> 2;  cA[u] = (e & 3) * 8;
        rB[u] = e >> 4;  cB[u] = (e & 15) * 8;
    }

    uint4 pAh[2], pAl[2], pBh[2], pBl[2];
#pragma unroll
    for (int u = 0; u < 2; u++) {
        pAh[u] = *(const uint4*)&Ahi[(size_t)rA[u] * 512 + cA[u]];
        pAl[u] = *(const uint4*)&Alo[(size_t)rA[u] * 512 + cA[u]];
        pBh[u] = *(const uint4*)&g_w2_hi[(size_t)rB[u] * 512 + ccol + cB[u]];
        pBl[u] = *(const uint4*)&g_w2_lo[(size_t)rB[u] * 512 + ccol + cB[u]];
    }

    for (int kt = 0; kt < 16; kt++) {
        if (kt) __syncthreads();
#pragma unroll
        for (int u = 0; u < 2; u++) {
            *(uint4*)&sAhi[rA[u] * AST + cA[u]] = pAh[u];
            *(uint4*)&sAlo[rA[u] * AST + cA[u]] = pAl[u];
            *(uint4*)&sBhi[rB[u] * BST + cB[u]] = pBh[u];
            *(uint4*)&sBlo[rB[u] * BST + cB[u]] = pBl[u];
        }
        __syncthreads();

        if (kt + 1 < 16) {
            int k0 = (kt + 1) * 32;
#pragma unroll
            for (int u = 0; u < 2; u++) {
                pAh[u] = *(const uint4*)&Ahi[(size_t)rA[u] * 512 + k0 + cA[u]];
                pAl[u] = *(const uint4*)&Alo[(size_t)rA[u] * 512 + k0 + cA[u]];
                pBh[u] = *(const uint4*)&g_w2_hi[(size_t)(k0 + rB[u]) * 512 + ccol + cB[u]];
                pBl[u] = *(const uint4*)&g_w2_lo[(size_t)(k0 + rB[u]) * 512 + ccol + cB[u]];
            }
        }

#pragma unroll
        for (int ks = 0; ks < 2; ks++) {
            int kk = ks * 16;
            uint32_t afh[4][4], afl[4][4], bfh[4][2], bfl[4][2];
#pragma unroll
            for (int mi = 0; mi < 4; mi++) {
                int row = wm * 64 + mi * 16 + (lane & 15);
                int col = kk + ((lane >> 4) << 3);
                LDSM_X4(afh[mi][0], afh[mi][1], afh[mi][2], afh[mi][3],
                        smem_u32(&sAhi[row * AST + col]));
                LDSM_X4(afl[mi][0], afl[mi][1], afl[mi][2], afl[mi][3],
                        smem_u32(&sAlo[row * AST + col]));
            }
#pragma unroll
            for (int nq = 0; nq < 2; nq++) {
                int krow = kk + (lane & 15);
                int col  = wn * 32 + nq * 16 + ((lane >> 4) << 3);
                uint32_t r0, r1, r2, r3;
                LDSM_X4T(r0, r1, r2, r3, smem_u32(&sBhi[krow * BST + col]));
                bfh[nq * 2][0] = r0; bfh[nq * 2][1] = r1;
                bfh[nq * 2 + 1][0] = r2; bfh[nq * 2 + 1][1] = r3;
                LDSM_X4T(r0, r1, r2, r3, smem_u32(&sBlo[krow * BST + col]));
                bfl[nq * 2][0] = r0; bfl[nq * 2][1] = r1;
                bfl[nq * 2 + 1][0] = r2; bfl[nq * 2 + 1][1] = r3;
            }
#pragma unroll
            for (int mi = 0; mi < 4; mi++)
#pragma unroll
                for (int ni = 0; ni < 4; ni++) {
                    MMA_BF16(acc[mi][ni], afh[mi], bfh[ni]);
                    MMA_BF16(acc[mi][ni], afh[mi], bfl[ni]);
                    MMA_BF16(acc[mi][ni], afl[mi], bfh[ni]);
                }
        }
    }

    int gr = lane >> 2, gc = (lane & 3) * 2;
#pragma unroll
    for (int mi = 0; mi < 4; mi++)
#pragma unroll
        for (int ni = 0; ni < 4; ni++) {
            int rr = crow + wm * 64 + mi * 16 + gr;
            int cc = ccol + wn * 32 + ni * 8 + gc;
            float b0 = bias[cc], b1 = bias[cc + 1];
            C[(size_t)rr * 512 + cc]           = acc[mi][ni][0] + b0;
            C[(size_t)rr * 512 + cc + 1]       = acc[mi][ni][1] + b1;
            C[(size_t)(rr + 8) * 512 + cc]     = acc[mi][ni][2] + b0;
            C[(size_t)(rr + 8) * 512 + cc + 1] = acc[mi][ni][3] + b1;
        }
}

// ---------------- row LayerNorm over E=512 — one warp per row ----------------
__global__ __launch_bounds__(256) void ln_rows(
    const float* __restrict__ x, const float* __restrict__ g,
    const float* __restrict__ b, float* __restrict__ y)
{
    int warp = (blockIdx.x * 256 + threadIdx.x) >> 5;
    int lane = threadIdx.x & 31;
    const float* r = x + (size_t)warp * 512;

    float4 v[4];
    float s = 0.f;
#pragma unroll
    for (int i = 0; i < 4; i++) {
        v[i] = ((const float4*)r)[lane + 32 * i];
        s += v[i].x + v[i].y + v[i].z + v[i].w;
    }
#pragma unroll
    for (int off = 16; off > 0; off >>= 1) s += __shfl_xor_sync(0xffffffffu, s, off);
    float mu = s * (1.0f / 512.0f);

    float s2 = 0.f;
#pragma unroll
    for (int i = 0; i < 4; i++) {
        float dx;
        dx = v[i].x - mu; s2 = fmaf(dx, dx, s2);
        dx = v[i].y - mu; s2 = fmaf(dx, dx, s2);
        dx = v[i].z - mu; s2 = fmaf(dx, dx, s2);
        dx = v[i].w - mu; s2 = fmaf(dx, dx, s2);
    }
#pragma unroll
    for (int off = 16; off > 0; off >>= 1) s2 += __shfl_xor_sync(0xffffffffu, s2, off);
    float var = s2 * (1.0f / 512.0f);
    float inv = 1.0f / sqrtf(var + LN_EPS);

#pragma unroll
    for (int i = 0; i < 4; i++) {
        int e = 4 * (lane + 32 * i);
        float4 gg = *(const float4*)(g + e);
        float4 bb = *(const float4*)(b + e);
        float4 o;
        o.x = (v[i].x - mu) * inv * gg.x + bb.x;
        o.y = (v[i].y - mu) * inv * gg.y + bb.y;
        o.z = (v[i].z - mu) * inv * gg.z + bb.z;
        o.w = (v[i].w - mu) * inv * gg.w + bb.w;
        ((float4*)(y + (size_t)warp * 512))[lane + 32 * i] = o;
    }
}

// ---------------- gather: q rows, idx (as float), one-hot scatter ----------------
__global__ void gather_out(float* __restrict__ outq, float* __restrict__ outidx,
                           float* __restrict__ outenc)
{
    int tok = blockIdx.x;
    int k = (int)(g_key[tok] & 0xFFFFFFFFull);
    int t = threadIdx.x;
    float4 v = ((const float4*)(g_tbl + (size_t)k * 512))[t];
    ((float4*)(outq + (size_t)tok * 512))[t] = v;
    if (t == 0) {
        if (outidx) outidx[tok] = (float)k;
        if (outenc) outenc[(size_t)tok * K_CODES + k] = 1.0f;
    }
}

// ---------------- launch ----------------
extern "C" void kernel_launch(void* const* d_in, const int* in_sizes, int n_in,
                              void* d_out, int out_size)
{
    const float* features = (const float*)d_in[0];
    const float* W1_in    = (const float*)d_in[1];
    const float* b1_in    = (const float*)d_in[2];
    const float* W2_in    = (const float*)d_in[3];
    const float* b2_in    = (const float*)d_in[4];
    const float* ln_in_g  = (const float*)d_in[5];
    const float* ln_in_b  = (const float*)d_in[6];
    const float* emb      = (const float*)d_in[7];
    const float* W1_out   = (const float*)d_in[8];
    const float* b1_out   = (const float*)d_in[9];
    const float* W2_out   = (const float*)d_in[10];
    const float* b2_out   = (const float*)d_in[11];
    const float* ln_out_g = (const float*)d_in[12];
    const float* ln_out_b = (const float*)d_in[13];

    float* out = (float*)d_out;
    const long long q_elems   = (long long)N_TOK * E_DIM;
    const long long idx_elems = N_TOK;
    const long long enc_elems = (long long)N_TOK * K_CODES;
    float* outq   = out;
    float* outidx = nullptr;
    float* outenc = nullptr;
    if ((long long)out_size >= q_elems + idx_elems + enc_elems) {
        outidx = out + q_elems;
        outenc = out + q_elems + idx_elems;
    } else if ((long long)out_size >= q_elems + idx_elems) {
        outidx = out + q_elems;
    }

    float *p_h, *p_z, *p_tpre, *p_tbl;
    __nv_bfloat16 *p_fhi, *p_fmi, *p_flo, *p_w1hi, *p_w1mi, *p_w1lo;
    void* p_key;
    cudaGetSymbolAddress((void**)&p_h,    g_h);
    cudaGetSymbolAddress((void**)&p_z,    g_z);
    cudaGetSymbolAddress((void**)&p_tpre, g_tpre);
    cudaGetSymbolAddress((void**)&p_tbl,  g_tbl);
    cudaGetSymbolAddress((void**)&p_fhi,  g_fhi);
    cudaGetSymbolAddress((void**)&p_fmi,  g_fmi);
    cudaGetSymbolAddress((void**)&p_flo,  g_flo);
    cudaGetSymbolAddress((void**)&p_w1hi, g_w1hi);
    cudaGetSymbolAddress((void**)&p_w1mi, g_w1mi);
    cudaGetSymbolAddress((void**)&p_w1lo, g_w1lo);
    cudaGetSymbolAddress(&p_key, g_key);

    // streams: B = codebook table, C = encodings memset, D = hmma token pipeline
    static cudaStream_t sB = nullptr, sC = nullptr, sD = nullptr;
    static cudaEvent_t evF = nullptr, evB = nullptr, evC = nullptr, evD = nullptr,
                       evK = nullptr;
    if (!sB) {
        cudaStreamCreateWithFlags(&sB, cudaStreamNonBlocking);
        cudaStreamCreateWithFlags(&sC, cudaStreamNonBlocking);
        cudaStreamCreateWithFlags(&sD, cudaStreamNonBlocking);
        cudaEventCreateWithFlags(&evF, cudaEventDisableTiming);
        cudaEventCreateWithFlags(&evB, cudaEventDisableTiming);
        cudaEventCreateWithFlags(&evC, cudaEventDisableTiming);
        cudaEventCreateWithFlags(&evD, cudaEventDisableTiming);
        cudaEventCreateWithFlags(&evK, cudaEventDisableTiming);
    }

    cudaEventRecord(evF, 0);
    cudaStreamWaitEvent(sB, evF, 0);
    cudaStreamWaitEvent(sC, evF, 0);
    cudaStreamWaitEvent(sD, evF, 0);

    // ---- stream C: encodings memset (pure DRAM, hides under compute) ----
    if (outenc)
        cudaMemsetAsync(outenc, 0, (size_t)enc_elems * sizeof(float), sC);
    cudaEventRecord(evC, sC);

    // ---- stream B: codebook output table (validated bf16 tensor path) ----
    split_w2<<<(E_DIM * E_DIM) / 256, 256, 0, sB>>>(W2_out);
    proj_out1<<<(K_CODES * E_DIM) / 256, 256, 0, sB>>>(emb, W1_out, b1_out);
    dim3 g2(E_DIM / 128, K_CODES / 128);
    hmma_tbl<<<g2, 256, 0, sB>>>(b2_out, p_tpre);
    ln_rows<<<K_CODES / 8, 256, 0, sB>>>(p_tpre, ln_out_g, ln_out_b, p_tbl);
    cudaEventRecord(evB, sB);

    // ---- stream 0: g_key init (gates both argmin halves) ----
    cudaMemsetAsync(p_key, 0xFF, N_TOK * sizeof(unsigned long long), 0);
    cudaEventRecord(evK, 0);

    // ---- stream D: bf16 token pipeline (rows M_SPLIT..N_TOK) ----
    {
        const size_t off = (size_t)M_SPLIT * E_DIM;
        split3<<<((N_TOK - M_SPLIT) * E_DIM) / 256, 256, 0, sD>>>(
            features + off, p_fhi + off, p_fmi + off, p_flo + off);
        split3<<<(E_DIM * E_DIM) / 256, 256, 0, sD>>>(
            W1_in, p_w1hi, p_w1mi, p_w1lo);
        dim3 gd(E_DIM / 128, (N_TOK - M_SPLIT) / 128);
        hmma3_gemm1<<<gd, 256, 0, sD>>>(M_SPLIT, b1_in, p_h);
        gemm2_ln<<<(N_TOK - M_SPLIT) / 8, 256, 0, sD>>>(
            M_SPLIT, p_h, W2_in, b2_in, ln_in_g, ln_in_b, p_z);
        cudaStreamWaitEvent(sD, evK, 0);
        argmin_kernel<<<dim3(K_CODES / CHUNK, (N_TOK - M_SPLIT) / 1024), 256, 0, sD>>>(
            M_SPLIT, emb, p_z);
    }
    cudaEventRecord(evD, sD);

    // ---- stream 0: fp32 token pipeline (rows 0..M_SPLIT) ----
    dim3 g1(E_DIM / 128, M_SPLIT / 128);
    sgemm_bias<1><<<g1, 256>>>(M_SPLIT, E_DIM, E_DIM, features, W1_in, b1_in, p_h);
    gemm2_ln<<<M_SPLIT / 8, 256>>>(0, p_h, W2_in, b2_in, ln_in_g, ln_in_b, p_z);
    argmin_kernel<<<dim3(K_CODES / CHUNK, M_SPLIT / 1024), 256>>>(0, emb, p_z);

    // join + final gather
    cudaStreamWaitEvent(0, evD, 0);
    cudaStreamWaitEvent(0, evB, 0);
    cudaStreamWaitEvent(0, evC, 0);
    gather_out<<<N_TOK, 128>>>(outq, outidx, outenc);
}